// round 8
// baseline (speedup 1.0000x reference)
#include <cuda_runtime.h>
#include <math.h>

#define PI_D 3.14159265358979323846

// ----------------------------- scratch (device globals) -----------------------------
__device__ __align__(16) float2 g_S [32*200*400];   // row-FFT'd field, compact rows
__device__ __align__(16) float2 g_S2[32*200*400];   // after col FFT * trans * IFFT
__device__ float2 g_HT[3*400*400];    // transposed transfer functions [m][k][r]
__device__ float2 g_PH[4*200*200];    // precomputed layer phasors [l][i][j]
__device__ float  g_I [32*200*200];   // final intensity, logical layout
__device__ float  g_pool[625*32];     // pooled [p][b]
__device__ float  g_W1T[625*512];     // W1 transposed [p][hh]
__device__ float  g_R1[512];          // row sums of W1
__device__ float2 g_w400[400];        // e^{-2*pi*i*k/400}, fp64-initialized

// ----------------------------- complex helpers -----------------------------
__device__ __forceinline__ float2 cmul(float2 a, float2 b){
    return make_float2(fmaf(a.x,b.x,-a.y*b.y), fmaf(a.x,b.y, a.y*b.x));
}
__device__ __forceinline__ float2 cfma(float2 r, float2 a, float2 w){
    r.x = fmaf(a.x,w.x, fmaf(-a.y,w.y,r.x));
    r.y = fmaf(a.x,w.y, fmaf( a.y,w.x,r.y));
    return r;
}
template<bool INV>
__device__ __forceinline__ float2 TW(int m){   // W400^m (conj if INV)
    float2 v = g_w400[m];
    if (INV) v.y = -v.y;
    return v;
}

// ----------------------------- FFT-20 (registers): n=20, j=5*j1+j2, k=k1+4*k2 ------
// HZ:   inputs a[5..14] are identically zero (never read).
// CROP: only outputs k in {0..4, 15..19} are produced (a[5..14] left garbage).
template<bool INV, bool HZ, bool CROP>
__device__ __forceinline__ void fft20(float2* a){
    float2 t[20];
    #pragma unroll
    for (int j2=0;j2<5;j2++){
        float2 y0,y1,y2,y3;
        if (HZ){
            float2 x0=a[j2], x3=a[15+j2];
            y0 = make_float2(x0.x+x3.x, x0.y+x3.y);
            y2 = make_float2(x0.x-x3.x, x0.y-x3.y);
            if (!INV){ y1 = make_float2(x0.x - x3.y, x0.y + x3.x);   // x0 + i x3
                       y3 = make_float2(x0.x + x3.y, x0.y - x3.x); } // x0 - i x3
            else     { y1 = make_float2(x0.x + x3.y, x0.y - x3.x);
                       y3 = make_float2(x0.x - x3.y, x0.y + x3.x); }
        } else {
            float2 x0=a[j2], x1=a[5+j2], x2=a[10+j2], x3=a[15+j2];
            float2 s02=make_float2(x0.x+x2.x, x0.y+x2.y);
            float2 d02=make_float2(x0.x-x2.x, x0.y-x2.y);
            float2 s13=make_float2(x1.x+x3.x, x1.y+x3.y);
            float2 d13=make_float2(x1.x-x3.x, x1.y-x3.y);
            y0=make_float2(s02.x+s13.x, s02.y+s13.y);
            y2=make_float2(s02.x-s13.x, s02.y-s13.y);
            if (!INV){ y1=make_float2(d02.x+d13.y, d02.y-d13.x);   // d02 - i*d13
                       y3=make_float2(d02.x-d13.y, d02.y+d13.x); } // d02 + i*d13
            else     { y1=make_float2(d02.x-d13.y, d02.y+d13.x);
                       y3=make_float2(d02.x+d13.y, d02.y-d13.x); }
        }
        t[j2]    = y0;                                   // W20^m = W400^{20m} (broadcast)
        t[5+j2]  = cmul(y1, TW<INV>(20*j2));
        t[10+j2] = cmul(y2, TW<INV>(40*j2));
        t[15+j2] = cmul(y3, TW<INV>(60*j2));
    }
    const float C1f= 0.30901699437494742f, S1f=0.95105651629515357f;
    const float C2f=-0.80901699437494745f, S2f=0.58778525229247313f;
    const float si = INV ? 1.f : -1.f;
    const float2 w1=make_float2(C1f, si*S1f), w2=make_float2(C2f, si*S2f);
    const float2 w3=make_float2(C2f,-si*S2f), w4=make_float2(C1f,-si*S1f);
    #pragma unroll
    for (int k1=0;k1<4;k1++){
        float2 b0=t[k1*5], b1=t[k1*5+1], b2=t[k1*5+2], b3=t[k1*5+3], b4=t[k1*5+4];
        float2 y0=make_float2(b0.x+b1.x+b2.x+b3.x+b4.x, b0.y+b1.y+b2.y+b3.y+b4.y);
        a[k1]=y0;
        if (!CROP || k1==0){
            float2 y1=b0; y1=cfma(y1,b1,w1); y1=cfma(y1,b2,w2); y1=cfma(y1,b3,w3); y1=cfma(y1,b4,w4);
            a[k1+4]=y1;
        }
        if (!CROP){
            float2 y2=b0; y2=cfma(y2,b1,w2); y2=cfma(y2,b2,w4); y2=cfma(y2,b3,w1); y2=cfma(y2,b4,w3);
            a[k1+8]=y2;
        }
        if (!CROP || k1==3){
            float2 y3=b0; y3=cfma(y3,b1,w3); y3=cfma(y3,b2,w1); y3=cfma(y3,b3,w4); y3=cfma(y3,b4,w2);
            a[k1+12]=y3;
        }
        float2 y4=b0; y4=cfma(y4,b1,w4); y4=cfma(y4,b2,w3); y4=cfma(y4,b3,w2); y4=cfma(y4,b4,w1);
        a[k1+16]=y4;
    }
}

// ----------------------------- FFT-400 (warp, 20 active lanes), IN-PLACE buffer ----
// Single 422-slot buffer: stage1 writes the 21-stride tmp layout over the input
// (safe: every lane register-loads its full working set before any store, with
// __syncwarp separating the phases); stage2 writes natural order back.
template<bool INV, bool HZ, bool CROP>
__device__ void fft400(float2* __restrict__ buf, int lane){
    __syncwarp();
    float2 r[20];
    if (lane < 20){
        if (HZ){
            #pragma unroll
            for (int j1=0;j1<5;j1++)  r[j1]=buf[j1*20+lane];
            #pragma unroll
            for (int j1=15;j1<20;j1++) r[j1]=buf[j1*20+lane];
        } else {
            #pragma unroll
            for (int j1=0;j1<20;j1++) r[j1]=buf[j1*20+lane];
        }
    }
    __syncwarp();                                        // all reads done before overwrite
    if (lane < 20){
        fft20<INV,HZ,false>(r);                          // over j1
        // incremental twiddles (scattered loads reduced 19 -> 4)
        float2 Wa = TW<INV>(lane);
        float2 A5 = TW<INV>(5*lane);
        float2 A10= TW<INV>(10*lane);
        float2 A15= TW<INV>(15*lane);
        float2 W2 = cmul(Wa,Wa);
        float2 W3 = cmul(W2,Wa);
        float2 W4 = cmul(W3,Wa);
        r[1]=cmul(r[1],Wa);  r[2]=cmul(r[2],W2);
        r[3]=cmul(r[3],W3);  r[4]=cmul(r[4],W4);
        r[5]=cmul(r[5],A5);
        r[6]=cmul(r[6],cmul(A5,Wa));   r[7]=cmul(r[7],cmul(A5,W2));
        r[8]=cmul(r[8],cmul(A5,W3));   r[9]=cmul(r[9],cmul(A5,W4));
        r[10]=cmul(r[10],A10);
        r[11]=cmul(r[11],cmul(A10,Wa)); r[12]=cmul(r[12],cmul(A10,W2));
        r[13]=cmul(r[13],cmul(A10,W3)); r[14]=cmul(r[14],cmul(A10,W4));
        r[15]=cmul(r[15],A15);
        r[16]=cmul(r[16],cmul(A15,Wa)); r[17]=cmul(r[17],cmul(A15,W2));
        r[18]=cmul(r[18],cmul(A15,W3)); r[19]=cmul(r[19],cmul(A15,W4));
        #pragma unroll
        for (int k1=0;k1<20;k1++) buf[k1*21+lane]=r[k1]; // tmp layout (<=418)
    }
    __syncwarp();
    if (lane < 20){
        #pragma unroll
        for (int j2=0;j2<20;j2++) r[j2]=buf[lane*21+j2];
    }
    __syncwarp();                                        // all reads done before overwrite
    if (lane < 20){
        fft20<INV,false,CROP>(r);                        // over j2
        #pragma unroll
        for (int k2=0;k2<20;k2++)
            if (!CROP || k2<5 || k2>=15) buf[k2*20+lane]=r[k2]; // X[k1+20*k2]
    }
    __syncwarp();
}

#define WPB 4   // warps (transforms) per block for row-FFT kernels
#define BSTR 422  // per-transform buffer slots (>=421, float4-aligned)

// ----------------------------- init: twiddles + zero histogram -----------------------------
__global__ void kInit(float* out){
    int k = threadIdx.x;
    if (k < 400){
        double ang = -2.0*PI_D*(double)k/400.0;
        g_w400[k] = make_float2((float)cos(ang), (float)sin(ang));
    }
    if (k < 11) out[1250+k] = 0.f;
}

// ----------------------------- precompute layer phasors (unique (l,i,j) only) ------
__global__ void kPrep(const float* __restrict__ phase){
    int idx = blockIdx.x*256 + threadIdx.x;
    if (idx >= 4*40000) return;
    float p = phase[idx];
    float sv, cv;
    sincospif(2.f*(sinf(p)+1.f), &sv, &cv);   // e^{i*2*pi*(sin(p)+1)}
    g_PH[idx] = make_float2(cv, sv);
}

// ----------------------------- transpose transfer functions (tiled) -----------------------------
__global__ void kHT(const float2* __restrict__ t0, const float2* __restrict__ t1,
                    const float2* __restrict__ t2){
    __shared__ float2 tile[32][33];
    int m = blockIdx.z;
    const float2* src = (m==0)? t0 : (m==1)? t1 : t2;
    int r0 = blockIdx.y*32, k0 = blockIdx.x*32;
    int tx = threadIdx.x, ty = threadIdx.y;   // 32 x 8
    for (int yy=ty; yy<32; yy+=8){
        int r = r0+yy, k = k0+tx;
        if (r<400 && k<400) tile[yy][tx] = src[r*400+k];
    }
    __syncthreads();
    for (int yy=ty; yy<32; yy+=8){
        int k = k0+yy, r = r0+tx;
        if (r<400 && k<400) g_HT[(size_t)m*160000 + k*400 + r] = tile[tx][yy];
    }
}

// ----------------------------- W1 transpose (tiled) + row sums -----------------------------
__global__ void kT(const float* __restrict__ W1){
    __shared__ float tile[32][33];
    int p0 = blockIdx.x*32, h0 = blockIdx.y*32;
    int tx = threadIdx.x, ty = threadIdx.y;   // 32 x 8
    for (int yy=ty; yy<32; yy+=8){
        int hh = h0+yy, p = p0+tx;
        if (hh<512 && p<625) tile[yy][tx] = W1[hh*625+p];
    }
    __syncthreads();
    for (int yy=ty; yy<32; yy+=8){
        int p = p0+yy, hh = h0+tx;
        if (p<625 && hh<512) g_W1T[p*512+hh] = tile[tx][yy];
    }
}
__global__ void kR1(const float* __restrict__ W1){   // grid 512, block 128
    __shared__ float red[128];
    int hh = blockIdx.x, tid = threadIdx.x;
    float s = 0.f;
    for (int p=tid; p<625; p+=128) s += W1[hh*625+p];
    red[tid] = s;
    __syncthreads();
    for (int st=64; st>0; st>>=1){
        if (tid<st) red[tid]+=red[tid+st];
        __syncthreads();
    }
    if (tid==0) g_R1[hh] = red[0];
}

// ----------------------------- A0: real input -> row FFT -----------------------------
__global__ void kA0(const float* __restrict__ x){
    __shared__ __align__(16) float2 s_buf[WPB][BSTR];
    int w = threadIdx.x>>5, lane = threadIdx.x&31;
    int idx = blockIdx.x*WPB + w;
    int b = idx/200, c = idx%200;
    int i = (c<100)? c+100 : c-100;                 // logical row
    const float4* xr4 = (const float4*)(x + ((size_t)b*200 + i)*200);
    float2* lin = s_buf[w];
    if (lane < 25){
        float4 v = xr4[25+lane];                    // x[100..199] -> lin[0..99]
        lin[4*lane  ] = make_float2(v.x,0.f);
        lin[4*lane+1] = make_float2(v.y,0.f);
        lin[4*lane+2] = make_float2(v.z,0.f);
        lin[4*lane+3] = make_float2(v.w,0.f);
        float4 u = xr4[lane];                       // x[0..99]   -> lin[300..399]
        lin[300+4*lane  ] = make_float2(u.x,0.f);
        lin[300+4*lane+1] = make_float2(u.y,0.f);
        lin[300+4*lane+2] = make_float2(u.z,0.f);
        lin[300+4*lane+3] = make_float2(u.w,0.f);
    }
    fft400<false,true,false>(lin,lane);
    float4* out4 = (float4*)(g_S + ((size_t)b*200+c)*400);
    const float4* lin4 = (const float4*)lin;
    for (int m4=lane;m4<200;m4+=32) out4[m4]=lin4[m4];
}

// ----------------------------- B (warp-private): col FFT * trans * col IFFT --------
// One block: 8 adjacent freq-columns of one image, 128 threads (4 warps).
__global__ void __launch_bounds__(128) kB(int hm){
    __shared__ __align__(16) float2 colb[8][BSTR];
    int b  = blockIdx.x / 50;
    int k0 = (blockIdx.x % 50) * 8;
    int tid = threadIdx.x;
    const float4* Sb4 = (const float4*)(g_S + (size_t)b*200*400);
    const float2* HT = g_HT + (size_t)hm*160000;

    // stage in (float4 = 2 complex): col[kl][r], r in [0,100) U [300,400)
    for (int idx=tid; idx<800; idx+=128){
        int c = idx>>2, q = idx&3;
        float4 v = Sb4[c*200 + (k0>>1) + q];
        int r = (c<100)? c : c+200;
        colb[2*q  ][r] = make_float2(v.x,v.y);
        colb[2*q+1][r] = make_float2(v.z,v.w);
    }
    __syncthreads();

    int w = tid>>5, lane = tid&31;
    #pragma unroll
    for (int s=0; s<2; s++){
        int kl = 2*w + s;
        float2* col = colb[kl];
        fft400<false,true,false>(col, lane);            // fwd, half-zero input
        const float2* ht = HT + (size_t)(k0+kl)*400;
        for (int r=lane; r<400; r+=32) col[r] = cmul(col[r], ht[r]);  // coalesced
        fft400<true,false,true>(col, lane);             // inv, cropped output
    }
    __syncthreads();

    // stage out (float4), crop rows, scale 1/400
    float4* S2b4 = (float4*)(g_S2 + (size_t)b*200*400);
    const float sc = 1.f/400.f;
    for (int idx=tid; idx<800; idx+=128){
        int c = idx>>2, q = idx&3;
        int r = (c<100)? c : c+200;
        float2 v0 = colb[2*q  ][r];
        float2 v1 = colb[2*q+1][r];
        S2b4[c*200 + (k0>>1) + q] = make_float4(v0.x*sc, v0.y*sc, v1.x*sc, v1.y*sc);
    }
}

// ----------------------------- C: row IFFT + (phasor) + row FFT (fused) -----------
__global__ void kC(int l){   // l < 0: no phasor (first boundary)
    __shared__ __align__(16) float2 s_buf[WPB][BSTR];
    int w = threadIdx.x>>5, lane = threadIdx.x&31;
    int idx = blockIdx.x*WPB + w;
    int b = idx/200, c = idx%200;
    float2* lin = s_buf[w];
    const float4* S4 = (const float4*)(g_S2 + ((size_t)b*200+c)*400);
    float4* lin4 = (float4*)lin;
    for (int m4=lane;m4<200;m4+=32) lin4[m4]=S4[m4];
    fft400<true,false,true>(lin,lane);              // cropped inverse
    int i = (c<100)? c+100 : c-100;                 // logical row
    const float2* phrow = (l>=0)? (g_PH + (size_t)l*40000 + i*200) : nullptr;
    const float sc = 1.f/400.f;
    float2 keep[7];
    #pragma unroll
    for (int kk=0;kk<7;kk++){
        int cc = lane + kk*32;
        if (cc < 200){
            int rc = (cc<100)? cc : cc+200;
            float2 v = lin[rc];
            v.x *= sc; v.y *= sc;
            if (phrow){
                int j = (cc<100)? cc+100 : cc-100;
                v = cmul(v, phrow[j]);
            }
            keep[kk] = v;
        }
    }
    __syncwarp();
    #pragma unroll
    for (int kk=0;kk<7;kk++){
        int cc = lane + kk*32;
        if (cc < 200){
            int rc = (cc<100)? cc : cc+200;
            lin[rc] = keep[kk];
        }
    }
    fft400<false,true,false>(lin,lane);   // half-zero input: middle never read
    float4* out4 = (float4*)(g_S + ((size_t)b*200+c)*400);
    const float4* l4 = (const float4*)lin;
    for (int m4=lane;m4<200;m4+=32) out4[m4]=l4[m4];
}

// ----------------------------- CF: row IFFT -> intensity (logical layout) ----------
__global__ void kCF(){
    __shared__ __align__(16) float2 s_buf[WPB][BSTR];
    int w = threadIdx.x>>5, lane = threadIdx.x&31;
    int idx = blockIdx.x*WPB + w;
    int b = idx/200, c = idx%200;
    float2* lin = s_buf[w];
    const float4* S4 = (const float4*)(g_S2 + ((size_t)b*200+c)*400);
    float4* lin4 = (float4*)lin;
    for (int m4=lane;m4<200;m4+=32) lin4[m4]=S4[m4];
    fft400<true,false,true>(lin,lane);              // cropped inverse
    int i = (c<100)? c+100 : c-100;
    float* Ib = g_I + (size_t)b*40000 + i*200;
    const float sc = 1.f/400.f;
    for (int cc=lane;cc<200;cc+=32){
        int rc = (cc<100)? cc : cc+200;
        int j  = (cc<100)? cc+100 : cc-100;
        float vx = lin[rc].x*sc, vy = lin[rc].y*sc;
        Ib[j] = vx*vx + vy*vy;
    }
}

// ----------------------------- pooling: 8x8 mean -> [p][b], p-fastest mapping ------
__global__ void kPool(){
    int idx = blockIdx.x*256 + threadIdx.x;
    if (idx >= 20000) return;
    int b = idx / 625, p = idx % 625;     // adjacent threads: adjacent p
    int mi = p/25, mj = p%25;
    const float* base = g_I + (size_t)b*40000 + mi*8*200 + mj*8;
    float s = 0.f;
    #pragma unroll
    for (int u=0;u<8;u++)
        #pragma unroll
        for (int v=0;v<8;v++) s += base[u*200+v];
    g_pool[p*32+b] = s*(1.f/64.f);
}

// ----------------------------- per-window MLP + voting -----------------------------
#define HSTR 513    // padded hid stride (bank-conflict-free)
__global__ void __launch_bounds__(256) kWin(
                     const float* __restrict__ b1, const float* __restrict__ W2,
                     const float* __restrict__ b2, const float* __restrict__ gamma,
                     const float* __restrict__ beta, float* __restrict__ out)
{
    extern __shared__ float dsm[];
    float* swin = dsm;                    // [cell][b] up to 25*32
    float* hid  = dsm + 800;              // [b][hh] 32*HSTR
    float* lg   = dsm + 800 + 32*HSTR;    // [b][o]  32*10
    __shared__ double red1[256], red2[256];
    __shared__ int   pidx[25];
    __shared__ float s_inv, s_c0;
    __shared__ int   s_a[32];
    __shared__ float s_delta[32];

    int wI = blockIdx.x;
    int i = wI/25, j = wI%25;
    int wr = min(5, 25-i), wc = min(5, 25-j);
    int cells = wr*wc;
    int tid = threadIdx.x;
    if (tid < cells) pidx[tid] = (i + tid/wc)*25 + (j + tid%wc);
    __syncthreads();

    double s1 = 0.0, s2 = 0.0;
    for (int q=tid; q<cells*32; q+=256){
        int cell = q>>5, b = q&31;
        float v = g_pool[pidx[cell]*32 + b];
        swin[q] = v;
        s1 += v; s2 += (double)v*(double)v;
    }
    red1[tid]=s1; red2[tid]=s2;
    __syncthreads();
    for (int st=128; st>0; st>>=1){
        if (tid<st){ red1[tid]+=red1[tid+st]; red2[tid]+=red2[tid+st]; }
        __syncthreads();
    }
    if (tid == 0){
        double mu  = red1[0]/20000.0;
        double var = red2[0]/20000.0 - mu*mu;
        float inv = gamma[0]/(float)sqrt(var + 1e-5);
        s_inv = inv;
        s_c0  = beta[0] - (float)mu*inv;
    }
    __syncthreads();
    float inv = s_inv, c0 = s_c0;

    // hid[b][hh] = relu(c0*R1 + inv*<win,W1win> + b1); 8 batches per thread.
    for (int it=0; it<8; it++){
        int task = it*256 + tid;          // 2048 tasks = 4 bgroups x 512 hh
        int hh = task & 511, bg = task >> 9;
        float acc[8];
        #pragma unroll
        for (int u=0;u<8;u++) acc[u]=0.f;
        for (int cell=0; cell<cells; cell++){
            float wv = g_W1T[pidx[cell]*512+hh];
            const float* sw = swin + cell*32 + bg*8;
            #pragma unroll
            for (int u=0;u<8;u++) acc[u] = fmaf(sw[u], wv, acc[u]);
        }
        float base = fmaf(c0, g_R1[hh], b1[hh]);
        #pragma unroll
        for (int u=0;u<8;u++){
            float pre = fmaf(inv, acc[u], base);
            hid[(bg*8+u)*HSTR + hh] = fmaxf(pre, 0.f);
        }
    }
    __syncthreads();

    for (int t=tid; t<320; t+=256){
        int b = t/10, oo = t%10;
        float acc = b2[oo];
        const float* hb = hid + b*HSTR;
        const float* wv = W2 + oo*512;
        for (int hh=0; hh<512; hh++) acc = fmaf(hb[hh], wv[hh], acc);
        lg[b*10+oo] = acc;
    }
    __syncthreads();

    if (tid < 32){
        int b = tid;
        float lmax = lg[b*10], lmin = lg[b*10];
        int am = 0;
        for (int oo=1;oo<10;oo++){
            float v = lg[b*10+oo];
            if (v > lmax){ lmax = v; am = oo; }
            if (v < lmin)  lmin = v;
        }
        float se = 0.f;
        for (int oo=0;oo<10;oo++) se += expf(lg[b*10+oo]-lmax);
        s_a[b] = am;
        s_delta[b] = (1.f - expf(lmin-lmax))/se;  // pmax - pmin
    }
    __syncthreads();
    if (tid == 0){
        int votes[11];
        for (int k=0;k<11;k++) votes[k]=0;
        for (int b=0;b<32;b++) votes[s_a[b]]++;
        int f0 = 0, best = votes[0];
        for (int k=1;k<11;k++) if (votes[k] > best){ best = votes[k]; f0 = k; }
        float sum = 0.f; int cnt = 0;
        for (int b=0;b<32;b++)
            if (s_a[b]==f0 && s_delta[b]!=0.f){ sum += s_delta[b]; cnt++; }
        int fin;
        if (cnt > 0){ float d1 = sum/(float)cnt; fin = (d1 < 0.2f) ? 0 : f0+1; }
        else fin = f0+1;   // delta1 = NaN; NaN < THR is false
        out[wI]       = (fin==0) ? 0.f : (float)fin;
        out[625+wI]   = (fin!=0) ? 1.f : 0.f;
        atomicAdd(&out[1250+fin], 1.0f);   // exact integer counts -> deterministic
    }
}

// ----------------------------- launch -----------------------------
extern "C" void kernel_launch(void* const* d_in, const int* in_sizes, int n_in,
                              void* d_out, int out_size)
{
    int o = (n_in >= 12 && in_sizes[1] == 1) ? 1 : 0;  // skip batch_size scalar if present
    const float*  x     = (const float*) d_in[0];
    const float2* h     = (const float2*)d_in[1+o];
    const float2* h_pro = (const float2*)d_in[2+o];
    const float2* h_det = (const float2*)d_in[3+o];
    const float*  phase = (const float*) d_in[4+o];
    const float*  W1    = (const float*) d_in[5+o];
    const float*  b1    = (const float*) d_in[6+o];
    const float*  W2    = (const float*) d_in[7+o];
    const float*  b2    = (const float*) d_in[8+o];
    const float*  gamma = (const float*) d_in[9+o];
    const float*  beta  = (const float*) d_in[10+o];
    float* out = (float*)d_out;

    cudaFuncSetAttribute(kWin, cudaFuncAttributeMaxDynamicSharedMemorySize,
                         (800 + 32*HSTR + 320)*4);

    kInit<<<1,512>>>(out);
    kPrep<<<625,256>>>(phase);
    kHT <<<dim3(13,13,3),dim3(32,8)>>>(h_pro, h, h_det);   // [0]=h_pro, [1]=h, [2]=h_det
    kT  <<<dim3(20,16),dim3(32,8)>>>(W1);
    kR1 <<<512,128>>>(W1);

    kA0 <<<1600,128>>>(x);
    kB  <<<1600,128>>>(0);                 // h_pro
    kC  <<<1600,128>>>(-1);
    for (int l=0; l<4; l++){
        kB <<<1600,128>>>(1);              // h (transposed once, reused 4x)
        kC <<<1600,128>>>(l);
    }
    kB  <<<1600,128>>>(2);                 // h_det
    kCF <<<1600,128>>>();

    kPool<<<79,256>>>();

    kWin<<<625,256,(800 + 32*HSTR + 320)*4>>>(b1, W2, b2, gamma, beta, out);
}

// round 9
// speedup vs baseline: 1.0708x; 1.0708x over previous
#include <cuda_runtime.h>
#include <math.h>

#define PI_D 3.14159265358979323846

// ----------------------------- scratch (device globals) -----------------------------
__device__ __align__(16) float2 g_S [32*200*400];   // row-FFT'd field, compact rows
__device__ __align__(16) float2 g_S2[32*200*400];   // after col FFT * trans * IFFT
__device__ float2 g_HT[3*400*400];    // transposed transfer functions [m][k][r], pre-scaled 1/400
__device__ float2 g_PH[4*200*200];    // precomputed layer phasors [l][i][j], pre-scaled 1/400
__device__ float  g_I [32*200*200];   // final intensity, logical layout
__device__ float  g_pool[625*32];     // pooled [p][b]
__device__ float  g_W1T[625*512];     // W1 transposed [p][hh]
__device__ float  g_R1[512];          // row sums of W1
__device__ float2 g_w400[400];        // e^{-2*pi*i*k/400}, fp64-initialized

// ----------------------------- complex helpers -----------------------------
__device__ __forceinline__ float2 cmul(float2 a, float2 b){
    return make_float2(fmaf(a.x,b.x,-a.y*b.y), fmaf(a.x,b.y, a.y*b.x));
}
__device__ __forceinline__ float2 cfma(float2 r, float2 a, float2 w){
    r.x = fmaf(a.x,w.x, fmaf(-a.y,w.y,r.x));
    r.y = fmaf(a.x,w.y, fmaf( a.y,w.x,r.y));
    return r;
}
template<bool INV>
__device__ __forceinline__ float2 TW(int m){   // W400^m (conj if INV)
    float2 v = g_w400[m];
    if (INV) v.y = -v.y;
    return v;
}

// ----------------------------- FFT-20 (registers): n=20, j=5*j1+j2, k=k1+4*k2 ------
// HZ:   inputs a[5..14] are identically zero (never read).
// CROP: only outputs k in {0..4, 15..19} are produced (a[5..14] left garbage).
template<bool INV, bool HZ, bool CROP>
__device__ __forceinline__ void fft20(float2* a){
    float2 t[20];
    #pragma unroll
    for (int j2=0;j2<5;j2++){
        float2 y0,y1,y2,y3;
        if (HZ){
            float2 x0=a[j2], x3=a[15+j2];
            y0 = make_float2(x0.x+x3.x, x0.y+x3.y);
            y2 = make_float2(x0.x-x3.x, x0.y-x3.y);
            if (!INV){ y1 = make_float2(x0.x - x3.y, x0.y + x3.x);   // x0 + i x3
                       y3 = make_float2(x0.x + x3.y, x0.y - x3.x); } // x0 - i x3
            else     { y1 = make_float2(x0.x + x3.y, x0.y - x3.x);
                       y3 = make_float2(x0.x - x3.y, x0.y + x3.x); }
        } else {
            float2 x0=a[j2], x1=a[5+j2], x2=a[10+j2], x3=a[15+j2];
            float2 s02=make_float2(x0.x+x2.x, x0.y+x2.y);
            float2 d02=make_float2(x0.x-x2.x, x0.y-x2.y);
            float2 s13=make_float2(x1.x+x3.x, x1.y+x3.y);
            float2 d13=make_float2(x1.x-x3.x, x1.y-x3.y);
            y0=make_float2(s02.x+s13.x, s02.y+s13.y);
            y2=make_float2(s02.x-s13.x, s02.y-s13.y);
            if (!INV){ y1=make_float2(d02.x+d13.y, d02.y-d13.x);   // d02 - i*d13
                       y3=make_float2(d02.x-d13.y, d02.y+d13.x); } // d02 + i*d13
            else     { y1=make_float2(d02.x-d13.y, d02.y+d13.x);
                       y3=make_float2(d02.x+d13.y, d02.y-d13.x); }
        }
        t[j2]    = y0;                                   // W20^m = W400^{20m} (broadcast)
        t[5+j2]  = cmul(y1, TW<INV>(20*j2));
        t[10+j2] = cmul(y2, TW<INV>(40*j2));
        t[15+j2] = cmul(y3, TW<INV>(60*j2));
    }
    const float C1f= 0.30901699437494742f, S1f=0.95105651629515357f;
    const float C2f=-0.80901699437494745f, S2f=0.58778525229247313f;
    const float si = INV ? 1.f : -1.f;
    const float2 w1=make_float2(C1f, si*S1f), w2=make_float2(C2f, si*S2f);
    const float2 w3=make_float2(C2f,-si*S2f), w4=make_float2(C1f,-si*S1f);
    #pragma unroll
    for (int k1=0;k1<4;k1++){
        float2 b0=t[k1*5], b1=t[k1*5+1], b2=t[k1*5+2], b3=t[k1*5+3], b4=t[k1*5+4];
        float2 y0=make_float2(b0.x+b1.x+b2.x+b3.x+b4.x, b0.y+b1.y+b2.y+b3.y+b4.y);
        a[k1]=y0;
        if (!CROP || k1==0){
            float2 y1=b0; y1=cfma(y1,b1,w1); y1=cfma(y1,b2,w2); y1=cfma(y1,b3,w3); y1=cfma(y1,b4,w4);
            a[k1+4]=y1;
        }
        if (!CROP){
            float2 y2=b0; y2=cfma(y2,b1,w2); y2=cfma(y2,b2,w4); y2=cfma(y2,b3,w1); y2=cfma(y2,b4,w3);
            a[k1+8]=y2;
        }
        if (!CROP || k1==3){
            float2 y3=b0; y3=cfma(y3,b1,w3); y3=cfma(y3,b2,w1); y3=cfma(y3,b3,w4); y3=cfma(y3,b4,w2);
            a[k1+12]=y3;
        }
        float2 y4=b0; y4=cfma(y4,b1,w4); y4=cfma(y4,b2,w3); y4=cfma(y4,b3,w2); y4=cfma(y4,b4,w1);
        a[k1+16]=y4;
    }
}

// ----------------------------- FFT-400 (warp, 20 active lanes): 20x20 four-step ----
// PM=0: plain stage-1 loads.
// PM=1: stage-1 load multiplies by pm[idx] (full 400 table; use with HZ=false).
// PM=2: stage-1 load multiplies by phasor pm[map(idx)] (corners; use with HZ=true);
//       if pm==nullptr, multiplies by scalar sc instead.
template<bool INV, bool HZ, bool CROP, int PM>
__device__ void fft400(float2* __restrict__ lin, float2* __restrict__ tmp, int lane,
                       const float2* __restrict__ pm = nullptr, float sc = 1.f){
    __syncwarp();
    float2 r[20];
    if (lane < 20){
        if (HZ){
            #pragma unroll
            for (int j1=0;j1<5;j1++){
                int idx=j1*20+lane;
                float2 v=lin[idx];
                if (PM==2) v = pm ? cmul(v, pm[idx+100]) : make_float2(v.x*sc, v.y*sc);
                r[j1]=v;
            }
            #pragma unroll
            for (int j1=15;j1<20;j1++){
                int idx=j1*20+lane;
                float2 v=lin[idx];
                if (PM==2) v = pm ? cmul(v, pm[idx-300]) : make_float2(v.x*sc, v.y*sc);
                r[j1]=v;
            }
        } else {
            #pragma unroll
            for (int j1=0;j1<20;j1++){
                int idx=j1*20+lane;
                float2 v=lin[idx];
                if (PM==1) v = cmul(v, pm[idx]);
                r[j1]=v;
            }
        }
        fft20<INV,HZ,false>(r);                          // over j1
        // incremental twiddles (scattered loads reduced 19 -> 4)
        float2 Wa = TW<INV>(lane);
        float2 A5 = TW<INV>(5*lane);
        float2 A10= TW<INV>(10*lane);
        float2 A15= TW<INV>(15*lane);
        float2 W2 = cmul(Wa,Wa);
        float2 W3 = cmul(W2,Wa);
        float2 W4 = cmul(W3,Wa);
        r[1]=cmul(r[1],Wa);  r[2]=cmul(r[2],W2);
        r[3]=cmul(r[3],W3);  r[4]=cmul(r[4],W4);
        r[5]=cmul(r[5],A5);
        r[6]=cmul(r[6],cmul(A5,Wa));   r[7]=cmul(r[7],cmul(A5,W2));
        r[8]=cmul(r[8],cmul(A5,W3));   r[9]=cmul(r[9],cmul(A5,W4));
        r[10]=cmul(r[10],A10);
        r[11]=cmul(r[11],cmul(A10,Wa)); r[12]=cmul(r[12],cmul(A10,W2));
        r[13]=cmul(r[13],cmul(A10,W3)); r[14]=cmul(r[14],cmul(A10,W4));
        r[15]=cmul(r[15],A15);
        r[16]=cmul(r[16],cmul(A15,Wa)); r[17]=cmul(r[17],cmul(A15,W2));
        r[18]=cmul(r[18],cmul(A15,W3)); r[19]=cmul(r[19],cmul(A15,W4));
        #pragma unroll
        for (int k1=0;k1<20;k1++) tmp[k1*21+lane]=r[k1];
    }
    __syncwarp();
    if (lane < 20){
        #pragma unroll
        for (int j2=0;j2<20;j2++) r[j2]=tmp[lane*21+j2];
        fft20<INV,false,CROP>(r);                        // over j2
        #pragma unroll
        for (int k2=0;k2<20;k2++)
            if (!CROP || k2<5 || k2>=15) lin[k2*20+lane]=r[k2]; // X[k1+20*k2]
    }
    __syncwarp();
}

#define WPB 4  // warps (transforms) per block for row-FFT kernels

// ----------------------------- init: twiddles + zero histogram -----------------------------
__global__ void kInit(float* out){
    int k = threadIdx.x;
    if (k < 400){
        double ang = -2.0*PI_D*(double)k/400.0;
        g_w400[k] = make_float2((float)cos(ang), (float)sin(ang));
    }
    if (k < 11) out[1250+k] = 0.f;
}

// ----------------------------- precompute layer phasors (pre-scaled by 1/400) ------
__global__ void kPrep(const float* __restrict__ phase){
    int idx = blockIdx.x*256 + threadIdx.x;
    if (idx >= 4*40000) return;
    float p = phase[idx];
    float sv, cv;
    sincospif(2.f*(sinf(p)+1.f), &sv, &cv);   // e^{i*2*pi*(sin(p)+1)}
    const float sc = 1.f/400.f;
    g_PH[idx] = make_float2(cv*sc, sv*sc);
}

// ----------------------------- transpose transfer functions (pre-scaled by 1/400) --
__global__ void kHT(const float2* __restrict__ t0, const float2* __restrict__ t1,
                    const float2* __restrict__ t2){
    __shared__ float2 tile[32][33];
    int m = blockIdx.z;
    const float2* src = (m==0)? t0 : (m==1)? t1 : t2;
    int r0 = blockIdx.y*32, k0 = blockIdx.x*32;
    int tx = threadIdx.x, ty = threadIdx.y;   // 32 x 8
    const float sc = 1.f/400.f;
    for (int yy=ty; yy<32; yy+=8){
        int r = r0+yy, k = k0+tx;
        if (r<400 && k<400) tile[yy][tx] = src[r*400+k];
    }
    __syncthreads();
    for (int yy=ty; yy<32; yy+=8){
        int k = k0+yy, r = r0+tx;
        if (r<400 && k<400){
            float2 v = tile[tx][yy];
            g_HT[(size_t)m*160000 + k*400 + r] = make_float2(v.x*sc, v.y*sc);
        }
    }
}

// ----------------------------- W1 transpose (tiled) + row sums -----------------------------
__global__ void kT(const float* __restrict__ W1){
    __shared__ float tile[32][33];
    int p0 = blockIdx.x*32, h0 = blockIdx.y*32;
    int tx = threadIdx.x, ty = threadIdx.y;   // 32 x 8
    for (int yy=ty; yy<32; yy+=8){
        int hh = h0+yy, p = p0+tx;
        if (hh<512 && p<625) tile[yy][tx] = W1[hh*625+p];
    }
    __syncthreads();
    for (int yy=ty; yy<32; yy+=8){
        int p = p0+yy, hh = h0+tx;
        if (p<625 && hh<512) g_W1T[p*512+hh] = tile[tx][yy];
    }
}
__global__ void kR1(const float* __restrict__ W1){   // grid 512, block 128
    __shared__ float red[128];
    int hh = blockIdx.x, tid = threadIdx.x;
    float s = 0.f;
    for (int p=tid; p<625; p+=128) s += W1[hh*625+p];
    red[tid] = s;
    __syncthreads();
    for (int st=64; st>0; st>>=1){
        if (tid<st) red[tid]+=red[tid+st];
        __syncthreads();
    }
    if (tid==0) g_R1[hh] = red[0];
}

// ----------------------------- A0: real input -> row FFT -----------------------------
__global__ void kA0(const float* __restrict__ x){
    __shared__ __align__(16) float2 s_lin[WPB][400];
    __shared__ float2 s_tmp[WPB][421];
    int w = threadIdx.x>>5, lane = threadIdx.x&31;
    int idx = blockIdx.x*WPB + w;
    int b = idx/200, c = idx%200;
    int i = (c<100)? c+100 : c-100;                 // logical row
    const float4* xr4 = (const float4*)(x + ((size_t)b*200 + i)*200);
    float2* lin = s_lin[w]; float2* tmp = s_tmp[w];
    if (lane < 25){
        float4 v = xr4[25+lane];                    // x[100..199] -> lin[0..99]
        lin[4*lane  ] = make_float2(v.x,0.f);
        lin[4*lane+1] = make_float2(v.y,0.f);
        lin[4*lane+2] = make_float2(v.z,0.f);
        lin[4*lane+3] = make_float2(v.w,0.f);
        float4 u = xr4[lane];                       // x[0..99]   -> lin[300..399]
        lin[300+4*lane  ] = make_float2(u.x,0.f);
        lin[300+4*lane+1] = make_float2(u.y,0.f);
        lin[300+4*lane+2] = make_float2(u.z,0.f);
        lin[300+4*lane+3] = make_float2(u.w,0.f);
    }
    fft400<false,true,false,0>(lin,tmp,lane);
    float4* out4 = (float4*)(g_S + ((size_t)b*200+c)*400);
    const float4* lin4 = (const float4*)lin;
    for (int m4=lane;m4<200;m4+=32) out4[m4]=lin4[m4];
}

// ----------------------------- B (warp-private): col FFT * trans * col IFFT --------
// One block: 8 adjacent freq-columns, 128 threads (4 warps). H-multiply fused into
// the inverse FFT's stage-1 loads; 1/400 scale folded into g_HT.
__global__ void __launch_bounds__(128) kB(int hm){
    __shared__ __align__(16) float2 colb[8][401];
    __shared__ float2 tmpb[4][421];
    int b  = blockIdx.x / 50;
    int k0 = (blockIdx.x % 50) * 8;
    int tid = threadIdx.x;
    const float4* Sb4 = (const float4*)(g_S + (size_t)b*200*400);
    const float2* HT = g_HT + (size_t)hm*160000;

    // stage in (float4 = 2 complex): col[kl][r], r in [0,100) U [300,400)
    for (int idx=tid; idx<800; idx+=128){
        int c = idx>>2, q = idx&3;
        float4 v = Sb4[c*200 + (k0>>1) + q];
        int r = (c<100)? c : c+200;
        colb[2*q  ][r] = make_float2(v.x,v.y);
        colb[2*q+1][r] = make_float2(v.z,v.w);
    }
    __syncthreads();

    int w = tid>>5, lane = tid&31;
    #pragma unroll
    for (int s=0; s<2; s++){
        int kl = 2*w + s;
        float2* col = colb[kl];
        fft400<false,true,false,0>(col, tmpb[w], lane);               // fwd, half-zero
        fft400<true,false,true,1>(col, tmpb[w], lane,
                                  HT + (size_t)(k0+kl)*400);          // inv, fused *H
    }
    __syncthreads();

    // stage out (float4), crop rows (no scale: folded into HT)
    float4* S2b4 = (float4*)(g_S2 + (size_t)b*200*400);
    for (int idx=tid; idx<800; idx+=128){
        int c = idx>>2, q = idx&3;
        int r = (c<100)? c : c+200;
        float2 v0 = colb[2*q  ][r];
        float2 v1 = colb[2*q+1][r];
        S2b4[c*200 + (k0>>1) + q] = make_float4(v0.x, v0.y, v1.x, v1.y);
    }
}

// ----------------------------- C: row IFFT + phasor + row FFT (fully fused) --------
__global__ void kC(int l){   // l < 0: no phasor (first boundary)
    __shared__ __align__(16) float2 s_lin[WPB][400];
    __shared__ float2 s_tmp[WPB][421];
    int w = threadIdx.x>>5, lane = threadIdx.x&31;
    int idx = blockIdx.x*WPB + w;
    int b = idx/200, c = idx%200;
    float2* lin = s_lin[w]; float2* tmp = s_tmp[w];
    const float4* S4 = (const float4*)(g_S2 + ((size_t)b*200+c)*400);
    float4* lin4 = (float4*)lin;
    for (int m4=lane;m4<200;m4+=32) lin4[m4]=S4[m4];
    fft400<true,false,true,0>(lin,tmp,lane);        // cropped inverse (corners valid)
    int i = (c<100)? c+100 : c-100;                 // logical row
    const float2* phrow = (l>=0)? (g_PH + (size_t)l*40000 + i*200) : nullptr;
    // forward FFT with phasor (pre-scaled 1/400) fused into stage-1 corner loads
    fft400<false,true,false,2>(lin,tmp,lane, phrow, 1.f/400.f);
    float4* out4 = (float4*)(g_S + ((size_t)b*200+c)*400);
    const float4* l4 = (const float4*)lin;
    for (int m4=lane;m4<200;m4+=32) out4[m4]=l4[m4];
}

// ----------------------------- CF: row IFFT -> intensity (logical layout) ----------
__global__ void kCF(){
    __shared__ __align__(16) float2 s_lin[WPB][400];
    __shared__ float2 s_tmp[WPB][421];
    int w = threadIdx.x>>5, lane = threadIdx.x&31;
    int idx = blockIdx.x*WPB + w;
    int b = idx/200, c = idx%200;
    float2* lin = s_lin[w]; float2* tmp = s_tmp[w];
    const float4* S4 = (const float4*)(g_S2 + ((size_t)b*200+c)*400);
    float4* lin4 = (float4*)lin;
    for (int m4=lane;m4<200;m4+=32) lin4[m4]=S4[m4];
    fft400<true,false,true,0>(lin,tmp,lane);        // cropped inverse
    int i = (c<100)? c+100 : c-100;
    float* Ib = g_I + (size_t)b*40000 + i*200;
    const float sc = 1.f/400.f;
    for (int cc=lane;cc<200;cc+=32){
        int rc = (cc<100)? cc : cc+200;
        int j  = (cc<100)? cc+100 : cc-100;
        float vx = lin[rc].x*sc, vy = lin[rc].y*sc;
        Ib[j] = vx*vx + vy*vy;
    }
}

// ----------------------------- pooling: 8x8 mean -> [p][b], p-fastest mapping ------
__global__ void kPool(){
    int idx = blockIdx.x*256 + threadIdx.x;
    if (idx >= 20000) return;
    int b = idx / 625, p = idx % 625;     // adjacent threads: adjacent p
    int mi = p/25, mj = p%25;
    const float* base = g_I + (size_t)b*40000 + mi*8*200 + mj*8;
    float s = 0.f;
    #pragma unroll
    for (int u=0;u<8;u++)
        #pragma unroll
        for (int v=0;v<8;v++) s += base[u*200+v];
    g_pool[p*32+b] = s*(1.f/64.f);
}

// ----------------------------- per-window MLP + voting -----------------------------
#define HSTR 513    // padded hid stride (bank-conflict-free)
__global__ void __launch_bounds__(256) kWin(
                     const float* __restrict__ b1, const float* __restrict__ W2,
                     const float* __restrict__ b2, const float* __restrict__ gamma,
                     const float* __restrict__ beta, float* __restrict__ out)
{
    extern __shared__ float dsm[];
    float* swin = dsm;                    // [cell][b] up to 25*32
    float* hid  = dsm + 800;              // [b][hh] 32*HSTR
    float* lg   = dsm + 800 + 32*HSTR;    // [b][o]  32*10
    __shared__ double red1[256], red2[256];
    __shared__ int   pidx[25];
    __shared__ float s_inv, s_c0;
    __shared__ int   s_a[32];
    __shared__ float s_delta[32];

    int wI = blockIdx.x;
    int i = wI/25, j = wI%25;
    int wr = min(5, 25-i), wc = min(5, 25-j);
    int cells = wr*wc;
    int tid = threadIdx.x;
    if (tid < cells) pidx[tid] = (i + tid/wc)*25 + (j + tid%wc);
    __syncthreads();

    double s1 = 0.0, s2 = 0.0;
    for (int q=tid; q<cells*32; q+=256){
        int cell = q>>5, b = q&31;
        float v = g_pool[pidx[cell]*32 + b];
        swin[q] = v;
        s1 += v; s2 += (double)v*(double)v;
    }
    red1[tid]=s1; red2[tid]=s2;
    __syncthreads();
    for (int st=128; st>0; st>>=1){
        if (tid<st){ red1[tid]+=red1[tid+st]; red2[tid]+=red2[tid+st]; }
        __syncthreads();
    }
    if (tid == 0){
        double mu  = red1[0]/20000.0;
        double var = red2[0]/20000.0 - mu*mu;
        float inv = gamma[0]/(float)sqrt(var + 1e-5);
        s_inv = inv;
        s_c0  = beta[0] - (float)mu*inv;
    }
    __syncthreads();
    float inv = s_inv, c0 = s_c0;

    // hid[b][hh] = relu(c0*R1 + inv*<win,W1win> + b1); 8 batches per thread.
    for (int it=0; it<8; it++){
        int task = it*256 + tid;          // 2048 tasks = 4 bgroups x 512 hh
        int hh = task & 511, bg = task >> 9;
        float acc[8];
        #pragma unroll
        for (int u=0;u<8;u++) acc[u]=0.f;
        for (int cell=0; cell<cells; cell++){
            float wv = g_W1T[pidx[cell]*512+hh];
            const float* sw = swin + cell*32 + bg*8;
            #pragma unroll
            for (int u=0;u<8;u++) acc[u] = fmaf(sw[u], wv, acc[u]);
        }
        float base = fmaf(c0, g_R1[hh], b1[hh]);
        #pragma unroll
        for (int u=0;u<8;u++){
            float pre = fmaf(inv, acc[u], base);
            hid[(bg*8+u)*HSTR + hh] = fmaxf(pre, 0.f);
        }
    }
    __syncthreads();

    for (int t=tid; t<320; t+=256){
        int b = t/10, oo = t%10;
        float acc = b2[oo];
        const float* hb = hid + b*HSTR;
        const float* wv = W2 + oo*512;
        for (int hh=0; hh<512; hh++) acc = fmaf(hb[hh], wv[hh], acc);
        lg[b*10+oo] = acc;
    }
    __syncthreads();

    if (tid < 32){
        int b = tid;
        float lmax = lg[b*10], lmin = lg[b*10];
        int am = 0;
        for (int oo=1;oo<10;oo++){
            float v = lg[b*10+oo];
            if (v > lmax){ lmax = v; am = oo; }
            if (v < lmin)  lmin = v;
        }
        float se = 0.f;
        for (int oo=0;oo<10;oo++) se += expf(lg[b*10+oo]-lmax);
        s_a[b] = am;
        s_delta[b] = (1.f - expf(lmin-lmax))/se;  // pmax - pmin
    }
    __syncthreads();
    if (tid == 0){
        int votes[11];
        for (int k=0;k<11;k++) votes[k]=0;
        for (int b=0;b<32;b++) votes[s_a[b]]++;
        int f0 = 0, best = votes[0];
        for (int k=1;k<11;k++) if (votes[k] > best){ best = votes[k]; f0 = k; }
        float sum = 0.f; int cnt = 0;
        for (int b=0;b<32;b++)
            if (s_a[b]==f0 && s_delta[b]!=0.f){ sum += s_delta[b]; cnt++; }
        int fin;
        if (cnt > 0){ float d1 = sum/(float)cnt; fin = (d1 < 0.2f) ? 0 : f0+1; }
        else fin = f0+1;   // delta1 = NaN; NaN < THR is false
        out[wI]       = (fin==0) ? 0.f : (float)fin;
        out[625+wI]   = (fin!=0) ? 1.f : 0.f;
        atomicAdd(&out[1250+fin], 1.0f);   // exact integer counts -> deterministic
    }
}

// ----------------------------- launch -----------------------------
extern "C" void kernel_launch(void* const* d_in, const int* in_sizes, int n_in,
                              void* d_out, int out_size)
{
    int o = (n_in >= 12 && in_sizes[1] == 1) ? 1 : 0;  // skip batch_size scalar if present
    const float*  x     = (const float*) d_in[0];
    const float2* h     = (const float2*)d_in[1+o];
    const float2* h_pro = (const float2*)d_in[2+o];
    const float2* h_det = (const float2*)d_in[3+o];
    const float*  phase = (const float*) d_in[4+o];
    const float*  W1    = (const float*) d_in[5+o];
    const float*  b1    = (const float*) d_in[6+o];
    const float*  W2    = (const float*) d_in[7+o];
    const float*  b2    = (const float*) d_in[8+o];
    const float*  gamma = (const float*) d_in[9+o];
    const float*  beta  = (const float*) d_in[10+o];
    float* out = (float*)d_out;

    cudaFuncSetAttribute(kWin, cudaFuncAttributeMaxDynamicSharedMemorySize,
                         (800 + 32*HSTR + 320)*4);

    kInit<<<1,512>>>(out);
    kPrep<<<625,256>>>(phase);
    kHT <<<dim3(13,13,3),dim3(32,8)>>>(h_pro, h, h_det);   // [0]=h_pro, [1]=h, [2]=h_det
    kT  <<<dim3(20,16),dim3(32,8)>>>(W1);
    kR1 <<<512,128>>>(W1);

    kA0 <<<1600,128>>>(x);
    kB  <<<1600,128>>>(0);                 // h_pro
    kC  <<<1600,128>>>(-1);
    for (int l=0; l<4; l++){
        kB <<<1600,128>>>(1);              // h (transposed once, reused 4x)
        kC <<<1600,128>>>(l);
    }
    kB  <<<1600,128>>>(2);                 // h_det
    kCF <<<1600,128>>>();

    kPool<<<79,256>>>();

    kWin<<<625,256,(800 + 32*HSTR + 320)*4>>>(b1, W2, b2, gamma, beta, out);
}

// round 10
// speedup vs baseline: 1.0752x; 1.0041x over previous
#include <cuda_runtime.h>
#include <math.h>

#define PI_D 3.14159265358979323846

// ----------------------------- scratch (device globals) -----------------------------
__device__ __align__(16) float2 g_S [32*200*400];   // row-FFT'd field, compact rows
__device__ __align__(16) float2 g_S2[32*200*400];   // after col FFT * trans * IFFT
__device__ float2 g_HT[3*400*400];    // transposed transfer functions [m][k][r], pre-scaled 1/400
__device__ float2 g_PH[4*200*200];    // precomputed layer phasors [l][i][j], pre-scaled 1/400
__device__ float  g_Pp[32*200*25];    // horizontal 8-sums of intensity [b][i][j8]
__device__ float  g_pool[625*32];     // pooled [p][b]
__device__ float  g_W1T[625*512];     // W1 transposed [p][hh]
__device__ float  g_R1[512];          // row sums of W1
__device__ float2 g_w400[400];        // e^{-2*pi*i*k/400}, fp64-initialized

// ----------------------------- complex helpers -----------------------------
__device__ __forceinline__ float2 cmul(float2 a, float2 b){
    return make_float2(fmaf(a.x,b.x,-a.y*b.y), fmaf(a.x,b.y, a.y*b.x));
}
__device__ __forceinline__ float2 cfma(float2 r, float2 a, float2 w){
    r.x = fmaf(a.x,w.x, fmaf(-a.y,w.y,r.x));
    r.y = fmaf(a.x,w.y, fmaf( a.y,w.x,r.y));
    return r;
}
template<bool INV>
__device__ __forceinline__ float2 TW(int m){   // W400^m (conj if INV)
    float2 v = g_w400[m];
    if (INV) v.y = -v.y;
    return v;
}

// ----------------------------- FFT-20 (registers): n=20, j=5*j1+j2, k=k1+4*k2 ------
// HZ:   inputs a[5..14] are identically zero (never read).
// CROP: only outputs k in {0..4, 15..19} are produced (a[5..14] left garbage).
template<bool INV, bool HZ, bool CROP>
__device__ __forceinline__ void fft20(float2* a){
    float2 t[20];
    #pragma unroll
    for (int j2=0;j2<5;j2++){
        float2 y0,y1,y2,y3;
        if (HZ){
            float2 x0=a[j2], x3=a[15+j2];
            y0 = make_float2(x0.x+x3.x, x0.y+x3.y);
            y2 = make_float2(x0.x-x3.x, x0.y-x3.y);
            if (!INV){ y1 = make_float2(x0.x - x3.y, x0.y + x3.x);   // x0 + i x3
                       y3 = make_float2(x0.x + x3.y, x0.y - x3.x); } // x0 - i x3
            else     { y1 = make_float2(x0.x + x3.y, x0.y - x3.x);
                       y3 = make_float2(x0.x - x3.y, x0.y + x3.x); }
        } else {
            float2 x0=a[j2], x1=a[5+j2], x2=a[10+j2], x3=a[15+j2];
            float2 s02=make_float2(x0.x+x2.x, x0.y+x2.y);
            float2 d02=make_float2(x0.x-x2.x, x0.y-x2.y);
            float2 s13=make_float2(x1.x+x3.x, x1.y+x3.y);
            float2 d13=make_float2(x1.x-x3.x, x1.y-x3.y);
            y0=make_float2(s02.x+s13.x, s02.y+s13.y);
            y2=make_float2(s02.x-s13.x, s02.y-s13.y);
            if (!INV){ y1=make_float2(d02.x+d13.y, d02.y-d13.x);   // d02 - i*d13
                       y3=make_float2(d02.x-d13.y, d02.y+d13.x); } // d02 + i*d13
            else     { y1=make_float2(d02.x-d13.y, d02.y+d13.x);
                       y3=make_float2(d02.x+d13.y, d02.y-d13.x); }
        }
        t[j2]    = y0;                                   // W20^m = W400^{20m} (broadcast)
        t[5+j2]  = cmul(y1, TW<INV>(20*j2));
        t[10+j2] = cmul(y2, TW<INV>(40*j2));
        t[15+j2] = cmul(y3, TW<INV>(60*j2));
    }
    const float C1f= 0.30901699437494742f, S1f=0.95105651629515357f;
    const float C2f=-0.80901699437494745f, S2f=0.58778525229247313f;
    const float si = INV ? 1.f : -1.f;
    const float2 w1=make_float2(C1f, si*S1f), w2=make_float2(C2f, si*S2f);
    const float2 w3=make_float2(C2f,-si*S2f), w4=make_float2(C1f,-si*S1f);
    #pragma unroll
    for (int k1=0;k1<4;k1++){
        float2 b0=t[k1*5], b1=t[k1*5+1], b2=t[k1*5+2], b3=t[k1*5+3], b4=t[k1*5+4];
        float2 y0=make_float2(b0.x+b1.x+b2.x+b3.x+b4.x, b0.y+b1.y+b2.y+b3.y+b4.y);
        a[k1]=y0;
        if (!CROP || k1==0){
            float2 y1=b0; y1=cfma(y1,b1,w1); y1=cfma(y1,b2,w2); y1=cfma(y1,b3,w3); y1=cfma(y1,b4,w4);
            a[k1+4]=y1;
        }
        if (!CROP){
            float2 y2=b0; y2=cfma(y2,b1,w2); y2=cfma(y2,b2,w4); y2=cfma(y2,b3,w1); y2=cfma(y2,b4,w3);
            a[k1+8]=y2;
        }
        if (!CROP || k1==3){
            float2 y3=b0; y3=cfma(y3,b1,w3); y3=cfma(y3,b2,w1); y3=cfma(y3,b3,w4); y3=cfma(y3,b4,w2);
            a[k1+12]=y3;
        }
        float2 y4=b0; y4=cfma(y4,b1,w4); y4=cfma(y4,b2,w3); y4=cfma(y4,b3,w2); y4=cfma(y4,b4,w1);
        a[k1+16]=y4;
    }
}

// ----------------------------- FFT-400 (warp, 20 active lanes): 20x20 four-step ----
// PM=0: plain stage-1 loads.
// PM=1: stage-1 load multiplies by pm[idx] (full 400 table; use with HZ=false).
// PM=2: stage-1 load multiplies by phasor pm[map(idx)] (corners; use with HZ=true);
//       if pm==nullptr, multiplies by scalar sc instead.
template<bool INV, bool HZ, bool CROP, int PM>
__device__ void fft400(float2* __restrict__ lin, float2* __restrict__ tmp, int lane,
                       const float2* __restrict__ pm = nullptr, float sc = 1.f){
    __syncwarp();
    float2 r[20];
    if (lane < 20){
        if (HZ){
            #pragma unroll
            for (int j1=0;j1<5;j1++){
                int idx=j1*20+lane;
                float2 v=lin[idx];
                if (PM==2) v = pm ? cmul(v, pm[idx+100]) : make_float2(v.x*sc, v.y*sc);
                r[j1]=v;
            }
            #pragma unroll
            for (int j1=15;j1<20;j1++){
                int idx=j1*20+lane;
                float2 v=lin[idx];
                if (PM==2) v = pm ? cmul(v, pm[idx-300]) : make_float2(v.x*sc, v.y*sc);
                r[j1]=v;
            }
        } else {
            #pragma unroll
            for (int j1=0;j1<20;j1++){
                int idx=j1*20+lane;
                float2 v=lin[idx];
                if (PM==1) v = cmul(v, pm[idx]);
                r[j1]=v;
            }
        }
        fft20<INV,HZ,false>(r);                          // over j1
        // incremental twiddles (scattered loads reduced 19 -> 4)
        float2 Wa = TW<INV>(lane);
        float2 A5 = TW<INV>(5*lane);
        float2 A10= TW<INV>(10*lane);
        float2 A15= TW<INV>(15*lane);
        float2 W2 = cmul(Wa,Wa);
        float2 W3 = cmul(W2,Wa);
        float2 W4 = cmul(W3,Wa);
        r[1]=cmul(r[1],Wa);  r[2]=cmul(r[2],W2);
        r[3]=cmul(r[3],W3);  r[4]=cmul(r[4],W4);
        r[5]=cmul(r[5],A5);
        r[6]=cmul(r[6],cmul(A5,Wa));   r[7]=cmul(r[7],cmul(A5,W2));
        r[8]=cmul(r[8],cmul(A5,W3));   r[9]=cmul(r[9],cmul(A5,W4));
        r[10]=cmul(r[10],A10);
        r[11]=cmul(r[11],cmul(A10,Wa)); r[12]=cmul(r[12],cmul(A10,W2));
        r[13]=cmul(r[13],cmul(A10,W3)); r[14]=cmul(r[14],cmul(A10,W4));
        r[15]=cmul(r[15],A15);
        r[16]=cmul(r[16],cmul(A15,Wa)); r[17]=cmul(r[17],cmul(A15,W2));
        r[18]=cmul(r[18],cmul(A15,W3)); r[19]=cmul(r[19],cmul(A15,W4));
        #pragma unroll
        for (int k1=0;k1<20;k1++) tmp[k1*21+lane]=r[k1];
    }
    __syncwarp();
    if (lane < 20){
        #pragma unroll
        for (int j2=0;j2<20;j2++) r[j2]=tmp[lane*21+j2];
        fft20<INV,false,CROP>(r);                        // over j2
        #pragma unroll
        for (int k2=0;k2<20;k2++)
            if (!CROP || k2<5 || k2>=15) lin[k2*20+lane]=r[k2]; // X[k1+20*k2]
    }
    __syncwarp();
}

#define WPB 4  // warps (transforms) per block for row-FFT kernels

// ----------------------------- init: twiddles + zero histogram -----------------------------
__global__ void kInit(float* out){
    int k = threadIdx.x;
    if (k < 400){
        double ang = -2.0*PI_D*(double)k/400.0;
        g_w400[k] = make_float2((float)cos(ang), (float)sin(ang));
    }
    if (k < 11) out[1250+k] = 0.f;
}

// ----------------------------- precompute layer phasors (pre-scaled by 1/400) ------
__global__ void kPrep(const float* __restrict__ phase){
    int idx = blockIdx.x*256 + threadIdx.x;
    if (idx >= 4*40000) return;
    float p = phase[idx];
    float sv, cv;
    sincospif(2.f*(sinf(p)+1.f), &sv, &cv);   // e^{i*2*pi*(sin(p)+1)}
    const float sc = 1.f/400.f;
    g_PH[idx] = make_float2(cv*sc, sv*sc);
}

// ----------------------------- transpose transfer functions (pre-scaled by 1/400) --
__global__ void kHT(const float2* __restrict__ t0, const float2* __restrict__ t1,
                    const float2* __restrict__ t2){
    __shared__ float2 tile[32][33];
    int m = blockIdx.z;
    const float2* src = (m==0)? t0 : (m==1)? t1 : t2;
    int r0 = blockIdx.y*32, k0 = blockIdx.x*32;
    int tx = threadIdx.x, ty = threadIdx.y;   // 32 x 8
    const float sc = 1.f/400.f;
    for (int yy=ty; yy<32; yy+=8){
        int r = r0+yy, k = k0+tx;
        if (r<400 && k<400) tile[yy][tx] = src[r*400+k];
    }
    __syncthreads();
    for (int yy=ty; yy<32; yy+=8){
        int k = k0+yy, r = r0+tx;
        if (r<400 && k<400){
            float2 v = tile[tx][yy];
            g_HT[(size_t)m*160000 + k*400 + r] = make_float2(v.x*sc, v.y*sc);
        }
    }
}

// ----------------------------- W1 transpose (tiled) + row sums -----------------------------
__global__ void kT(const float* __restrict__ W1){
    __shared__ float tile[32][33];
    int p0 = blockIdx.x*32, h0 = blockIdx.y*32;
    int tx = threadIdx.x, ty = threadIdx.y;   // 32 x 8
    for (int yy=ty; yy<32; yy+=8){
        int hh = h0+yy, p = p0+tx;
        if (hh<512 && p<625) tile[yy][tx] = W1[hh*625+p];
    }
    __syncthreads();
    for (int yy=ty; yy<32; yy+=8){
        int p = p0+yy, hh = h0+tx;
        if (p<625 && hh<512) g_W1T[p*512+hh] = tile[tx][yy];
    }
}
__global__ void kR1(const float* __restrict__ W1){   // grid 512, block 128
    __shared__ float red[128];
    int hh = blockIdx.x, tid = threadIdx.x;
    float s = 0.f;
    for (int p=tid; p<625; p+=128) s += W1[hh*625+p];
    red[tid] = s;
    __syncthreads();
    for (int st=64; st>0; st>>=1){
        if (tid<st) red[tid]+=red[tid+st];
        __syncthreads();
    }
    if (tid==0) g_R1[hh] = red[0];
}

// ----------------------------- A0: real input, 2 rows packed per complex FFT --------
// z = x_row0 + i*x_row1 (both share the half-zero corner structure), FFT once, unpack:
// X0[k] = (Z[k]+conj(Z[-k]))/2,  X1[k] = -i(Z[k]-conj(Z[-k]))/2.
__global__ void kA0(const float* __restrict__ x){   // grid 800, block 128
    __shared__ __align__(16) float2 s_lin[WPB][400];
    __shared__ float2 s_tmp[WPB][421];
    int w = threadIdx.x>>5, lane = threadIdx.x&31;
    int idx = blockIdx.x*WPB + w;                   // 0..3199 row-pairs
    int b = idx/100, pr = idx%100;
    int c0 = 2*pr, c1 = 2*pr+1;
    int i0 = (c0<100)? c0+100 : c0-100;             // logical rows
    int i1 = (c1<100)? c1+100 : c1-100;
    const float4* x0r4 = (const float4*)(x + ((size_t)b*200 + i0)*200);
    const float4* x1r4 = (const float4*)(x + ((size_t)b*200 + i1)*200);
    float2* lin = s_lin[w]; float2* tmp = s_tmp[w];
    if (lane < 25){
        float4 a0 = x0r4[25+lane], b0 = x1r4[25+lane];   // x[100..199] -> lin[0..99]
        lin[4*lane  ] = make_float2(a0.x, b0.x);
        lin[4*lane+1] = make_float2(a0.y, b0.y);
        lin[4*lane+2] = make_float2(a0.z, b0.z);
        lin[4*lane+3] = make_float2(a0.w, b0.w);
        float4 a1 = x0r4[lane],    b1 = x1r4[lane];      // x[0..99] -> lin[300..399]
        lin[300+4*lane  ] = make_float2(a1.x, b1.x);
        lin[300+4*lane+1] = make_float2(a1.y, b1.y);
        lin[300+4*lane+2] = make_float2(a1.z, b1.z);
        lin[300+4*lane+3] = make_float2(a1.w, b1.w);
    }
    fft400<false,true,false,0>(lin,tmp,lane);
    float2* row0 = g_S + ((size_t)b*200+c0)*400;
    float2* row1 = g_S + ((size_t)b*200+c1)*400;
    for (int k=lane; k<400; k+=32){
        float2 Zk = lin[k];
        float2 Zr = lin[(400-k) & 399];   // (400-k)%400; k=0 -> 0
        row0[k] = make_float2(0.5f*(Zk.x+Zr.x),  0.5f*(Zk.y-Zr.y));
        row1[k] = make_float2(0.5f*(Zk.y+Zr.y), -0.5f*(Zk.x-Zr.x));
    }
}

// ----------------------------- B (warp-private): col FFT * trans * col IFFT --------
// One block: 8 adjacent freq-columns, 128 threads (4 warps). H-multiply fused into
// the inverse FFT's stage-1 loads; 1/400 scale folded into g_HT.
// Column order: A.fwd, B.fwd, A.inv, B.inv (dependency-distance pipelining).
__global__ void __launch_bounds__(128) kB(int hm){
    __shared__ __align__(16) float2 colb[8][401];
    __shared__ float2 tmpb[4][421];
    int b  = blockIdx.x / 50;
    int k0 = (blockIdx.x % 50) * 8;
    int tid = threadIdx.x;
    const float4* Sb4 = (const float4*)(g_S + (size_t)b*200*400);
    const float2* HT = g_HT + (size_t)hm*160000;

    // stage in (float4 = 2 complex): col[kl][r], r in [0,100) U [300,400)
    for (int idx=tid; idx<800; idx+=128){
        int c = idx>>2, q = idx&3;
        float4 v = Sb4[c*200 + (k0>>1) + q];
        int r = (c<100)? c : c+200;
        colb[2*q  ][r] = make_float2(v.x,v.y);
        colb[2*q+1][r] = make_float2(v.z,v.w);
    }
    __syncthreads();

    int w = tid>>5, lane = tid&31;
    float2* colA = colb[2*w];
    float2* colB = colb[2*w+1];
    fft400<false,true,false,0>(colA, tmpb[w], lane);              // A fwd
    fft400<false,true,false,0>(colB, tmpb[w], lane);              // B fwd
    fft400<true,false,true,1>(colA, tmpb[w], lane,
                              HT + (size_t)(k0+2*w)*400);         // A inv, fused *H
    fft400<true,false,true,1>(colB, tmpb[w], lane,
                              HT + (size_t)(k0+2*w+1)*400);       // B inv, fused *H
    __syncthreads();

    // stage out (float4), crop rows (no scale: folded into HT)
    float4* S2b4 = (float4*)(g_S2 + (size_t)b*200*400);
    for (int idx=tid; idx<800; idx+=128){
        int c = idx>>2, q = idx&3;
        int r = (c<100)? c : c+200;
        float2 v0 = colb[2*q  ][r];
        float2 v1 = colb[2*q+1][r];
        S2b4[c*200 + (k0>>1) + q] = make_float4(v0.x, v0.y, v1.x, v1.y);
    }
}

// ----------------------------- C: row IFFT + phasor + row FFT (fully fused) --------
__global__ void kC(int l){   // l < 0: no phasor (first boundary)
    __shared__ __align__(16) float2 s_lin[WPB][400];
    __shared__ float2 s_tmp[WPB][421];
    int w = threadIdx.x>>5, lane = threadIdx.x&31;
    int idx = blockIdx.x*WPB + w;
    int b = idx/200, c = idx%200;
    float2* lin = s_lin[w]; float2* tmp = s_tmp[w];
    const float4* S4 = (const float4*)(g_S2 + ((size_t)b*200+c)*400);
    float4* lin4 = (float4*)lin;
    for (int m4=lane;m4<200;m4+=32) lin4[m4]=S4[m4];
    fft400<true,false,true,0>(lin,tmp,lane);        // cropped inverse (corners valid)
    int i = (c<100)? c+100 : c-100;                 // logical row
    const float2* phrow = (l>=0)? (g_PH + (size_t)l*40000 + i*200) : nullptr;
    // forward FFT with phasor (pre-scaled 1/400) fused into stage-1 corner loads
    fft400<false,true,false,2>(lin,tmp,lane, phrow, 1.f/400.f);
    float4* out4 = (float4*)(g_S + ((size_t)b*200+c)*400);
    const float4* l4 = (const float4*)lin;
    for (int m4=lane;m4<200;m4+=32) out4[m4]=l4[m4];
}

// ----------------------------- CF: row IFFT -> intensity -> horizontal 8-sums ------
__global__ void kCF(){
    __shared__ __align__(16) float2 s_lin[WPB][400];
    __shared__ float2 s_tmp[WPB][421];
    int w = threadIdx.x>>5, lane = threadIdx.x&31;
    int idx = blockIdx.x*WPB + w;
    int b = idx/200, c = idx%200;
    float2* lin = s_lin[w]; float2* tmp = s_tmp[w];
    const float4* S4 = (const float4*)(g_S2 + ((size_t)b*200+c)*400);
    float4* lin4 = (float4*)lin;
    for (int m4=lane;m4<200;m4+=32) lin4[m4]=S4[m4];
    fft400<true,false,true,0>(lin,tmp,lane);        // cropped inverse
    int i = (c<100)? c+100 : c-100;
    float* pbuf = (float*)tmp;                      // tmp is free now; 200 floats
    const float sc = 1.f/400.f;
    for (int cc=lane;cc<200;cc+=32){
        int rc = (cc<100)? cc : cc+200;
        int j  = (cc<100)? cc+100 : cc-100;
        float vx = lin[rc].x*sc, vy = lin[rc].y*sc;
        pbuf[j] = vx*vx + vy*vy;
    }
    __syncwarp();
    if (lane < 25){
        float s = 0.f;
        #pragma unroll
        for (int v=0; v<8; v++) s += pbuf[lane*8+v];
        g_Pp[((size_t)b*200+i)*25 + lane] = s;
    }
}

// ----------------------------- pooling: vertical sum of 8 partials -> [p][b] -------
__global__ void kPool(){
    int idx = blockIdx.x*256 + threadIdx.x;
    if (idx >= 20000) return;
    int b = idx / 625, p = idx % 625;
    int mi = p/25, mj = p%25;
    const float* base = g_Pp + ((size_t)b*200 + mi*8)*25 + mj;
    float s = 0.f;
    #pragma unroll
    for (int u=0;u<8;u++) s += base[u*25];
    g_pool[p*32+b] = s*(1.f/64.f);
}

// ----------------------------- per-window MLP + voting -----------------------------
#define HSTR 513    // padded hid stride (bank-conflict-free)
__global__ void __launch_bounds__(256) kWin(
                     const float* __restrict__ b1, const float* __restrict__ W2,
                     const float* __restrict__ b2, const float* __restrict__ gamma,
                     const float* __restrict__ beta, float* __restrict__ out)
{
    extern __shared__ float dsm[];
    float* swin = dsm;                    // [cell][b] up to 25*32
    float* hid  = dsm + 800;              // [b][hh] 32*HSTR
    float* lg   = dsm + 800 + 32*HSTR;    // [b][o]  32*10
    __shared__ double red1[256], red2[256];
    __shared__ int   pidx[25];
    __shared__ float s_inv, s_c0;
    __shared__ int   s_a[32];
    __shared__ float s_delta[32];

    int wI = blockIdx.x;
    int i = wI/25, j = wI%25;
    int wr = min(5, 25-i), wc = min(5, 25-j);
    int cells = wr*wc;
    int tid = threadIdx.x;
    if (tid < cells) pidx[tid] = (i + tid/wc)*25 + (j + tid%wc);
    __syncthreads();

    double s1 = 0.0, s2 = 0.0;
    for (int q=tid; q<cells*32; q+=256){
        int cell = q>>5, b = q&31;
        float v = g_pool[pidx[cell]*32 + b];
        swin[q] = v;
        s1 += v; s2 += (double)v*(double)v;
    }
    red1[tid]=s1; red2[tid]=s2;
    __syncthreads();
    for (int st=128; st>0; st>>=1){
        if (tid<st){ red1[tid]+=red1[tid+st]; red2[tid]+=red2[tid+st]; }
        __syncthreads();
    }
    if (tid == 0){
        double mu  = red1[0]/20000.0;
        double var = red2[0]/20000.0 - mu*mu;
        float inv = gamma[0]/(float)sqrt(var + 1e-5);
        s_inv = inv;
        s_c0  = beta[0] - (float)mu*inv;
    }
    __syncthreads();
    float inv = s_inv, c0 = s_c0;

    // hid[b][hh] = relu(c0*R1 + inv*<win,W1win> + b1); 8 batches per thread.
    for (int it=0; it<8; it++){
        int task = it*256 + tid;          // 2048 tasks = 4 bgroups x 512 hh
        int hh = task & 511, bg = task >> 9;
        float acc[8];
        #pragma unroll
        for (int u=0;u<8;u++) acc[u]=0.f;
        for (int cell=0; cell<cells; cell++){
            float wv = g_W1T[pidx[cell]*512+hh];
            const float* sw = swin + cell*32 + bg*8;
            #pragma unroll
            for (int u=0;u<8;u++) acc[u] = fmaf(sw[u], wv, acc[u]);
        }
        float base = fmaf(c0, g_R1[hh], b1[hh]);
        #pragma unroll
        for (int u=0;u<8;u++){
            float pre = fmaf(inv, acc[u], base);
            hid[(bg*8+u)*HSTR + hh] = fmaxf(pre, 0.f);
        }
    }
    __syncthreads();

    for (int t=tid; t<320; t+=256){
        int b = t/10, oo = t%10;
        float acc = b2[oo];
        const float* hb = hid + b*HSTR;
        const float* wv = W2 + oo*512;
        for (int hh=0; hh<512; hh++) acc = fmaf(hb[hh], wv[hh], acc);
        lg[b*10+oo] = acc;
    }
    __syncthreads();

    if (tid < 32){
        int b = tid;
        float lmax = lg[b*10], lmin = lg[b*10];
        int am = 0;
        for (int oo=1;oo<10;oo++){
            float v = lg[b*10+oo];
            if (v > lmax){ lmax = v; am = oo; }
            if (v < lmin)  lmin = v;
        }
        float se = 0.f;
        for (int oo=0;oo<10;oo++) se += expf(lg[b*10+oo]-lmax);
        s_a[b] = am;
        s_delta[b] = (1.f - expf(lmin-lmax))/se;  // pmax - pmin
    }
    __syncthreads();
    if (tid == 0){
        int votes[11];
        for (int k=0;k<11;k++) votes[k]=0;
        for (int b=0;b<32;b++) votes[s_a[b]]++;
        int f0 = 0, best = votes[0];
        for (int k=1;k<11;k++) if (votes[k] > best){ best = votes[k]; f0 = k; }
        float sum = 0.f; int cnt = 0;
        for (int b=0;b<32;b++)
            if (s_a[b]==f0 && s_delta[b]!=0.f){ sum += s_delta[b]; cnt++; }
        int fin;
        if (cnt > 0){ float d1 = sum/(float)cnt; fin = (d1 < 0.2f) ? 0 : f0+1; }
        else fin = f0+1;   // delta1 = NaN; NaN < THR is false
        out[wI]       = (fin==0) ? 0.f : (float)fin;
        out[625+wI]   = (fin!=0) ? 1.f : 0.f;
        atomicAdd(&out[1250+fin], 1.0f);   // exact integer counts -> deterministic
    }
}

// ----------------------------- launch -----------------------------
extern "C" void kernel_launch(void* const* d_in, const int* in_sizes, int n_in,
                              void* d_out, int out_size)
{
    int o = (n_in >= 12 && in_sizes[1] == 1) ? 1 : 0;  // skip batch_size scalar if present
    const float*  x     = (const float*) d_in[0];
    const float2* h     = (const float2*)d_in[1+o];
    const float2* h_pro = (const float2*)d_in[2+o];
    const float2* h_det = (const float2*)d_in[3+o];
    const float*  phase = (const float*) d_in[4+o];
    const float*  W1    = (const float*) d_in[5+o];
    const float*  b1    = (const float*) d_in[6+o];
    const float*  W2    = (const float*) d_in[7+o];
    const float*  b2    = (const float*) d_in[8+o];
    const float*  gamma = (const float*) d_in[9+o];
    const float*  beta  = (const float*) d_in[10+o];
    float* out = (float*)d_out;

    cudaFuncSetAttribute(kWin, cudaFuncAttributeMaxDynamicSharedMemorySize,
                         (800 + 32*HSTR + 320)*4);

    kInit<<<1,512>>>(out);
    kPrep<<<625,256>>>(phase);
    kHT <<<dim3(13,13,3),dim3(32,8)>>>(h_pro, h, h_det);   // [0]=h_pro, [1]=h, [2]=h_det
    kT  <<<dim3(20,16),dim3(32,8)>>>(W1);
    kR1 <<<512,128>>>(W1);

    kA0 <<<800,128>>>(x);                  // 2 rows per FFT (real packing)
    kB  <<<1600,128>>>(0);                 // h_pro
    kC  <<<1600,128>>>(-1);
    for (int l=0; l<4; l++){
        kB <<<1600,128>>>(1);              // h (transposed once, reused 4x)
        kC <<<1600,128>>>(l);
    }
    kB  <<<1600,128>>>(2);                 // h_det
    kCF <<<1600,128>>>();

    kPool<<<79,256>>>();

    kWin<<<625,256,(800 + 32*HSTR + 320)*4>>>(b1, W2, b2, gamma, beta, out);
}

// round 11
// speedup vs baseline: 1.1024x; 1.0253x over previous
#include <cuda_runtime.h>
#include <math.h>

#define PI_D 3.14159265358979323846
typedef unsigned long long ull;

// ----------------------------- scratch (device globals) -----------------------------
__device__ __align__(16) float2 g_S [32*200*400];   // row-FFT'd field, compact rows
__device__ __align__(16) float2 g_S2[32*200*400];   // after col FFT * trans * IFFT
__device__ float2 g_HT[3*400*400];    // transposed transfer functions [m][k][r], pre-scaled 1/400
__device__ float2 g_PH[4*200*200];    // precomputed layer phasors [l][i][j], pre-scaled 1/400
__device__ float  g_Pp[32*200*25];    // horizontal 8-sums of intensity [b][i][j8]
__device__ float  g_pool[625*32];     // pooled [p][b]
__device__ float  g_W1T[625*512];     // W1 transposed [p][hh]
__device__ float  g_R1[512];          // row sums of W1
__device__ float2 g_w400[400];        // e^{-2*pi*i*k/400}, fp64-initialized

// ----------------------------- packed f32x2 helpers (sm_100+) -----------------------
__device__ __forceinline__ ull F2U(float2 v){
    ull r; asm("mov.b64 %0, {%1,%2};" : "=l"(r) : "f"(v.x), "f"(v.y)); return r;
}
__device__ __forceinline__ float2 U2F(ull v){
    float2 r; asm("mov.b64 {%0,%1}, %2;" : "=f"(r.x), "=f"(r.y) : "l"(v)); return r;
}
__device__ __forceinline__ float2 add2(float2 a, float2 b){
    ull r; asm("add.rn.f32x2 %0, %1, %2;" : "=l"(r) : "l"(F2U(a)), "l"(F2U(b)));
    return U2F(r);
}
__device__ __forceinline__ float2 sub2(float2 a, float2 b){   // a - b == fma(b,-1,a), exact
    const ull N1 = 0xBF800000BF800000ULL;
    ull r; asm("fma.rn.f32x2 %0, %1, %2, %3;" : "=l"(r) : "l"(F2U(b)), "l"(N1), "l"(F2U(a)));
    return U2F(r);
}
__device__ __forceinline__ float2 fma2(ull a, ull b, float2 c){
    ull r; asm("fma.rn.f32x2 %0, %1, %2, %3;" : "=l"(r) : "l"(a), "l"(b), "l"(F2U(c)));
    return U2F(r);
}
__device__ __forceinline__ ull pkxx(float2 a){
    ull r; asm("mov.b64 %0, {%1,%2};" : "=l"(r) : "f"(a.x), "f"(a.x)); return r;
}
__device__ __forceinline__ ull pkny(float2 a){
    ull r; asm("mov.b64 %0, {%1,%2};" : "=l"(r) : "f"(-a.y), "f"(a.y)); return r;
}

// ----------------------------- complex helpers -----------------------------
__device__ __forceinline__ float2 cmul(float2 a, float2 b){
    return make_float2(fmaf(a.x,b.x,-a.y*b.y), fmaf(a.x,b.y, a.y*b.x));
}
__device__ __forceinline__ float2 cfma(float2 r, float2 a, float2 w){
    r.x = fmaf(a.x,w.x, fmaf(-a.y,w.y,r.x));
    r.y = fmaf(a.x,w.y, fmaf( a.y,w.x,r.y));
    return r;
}
template<bool INV>
__device__ __forceinline__ float2 TW(int m){   // W400^m (conj if INV)
    float2 v = g_w400[m];
    if (INV) v.y = -v.y;
    return v;
}

// ----------------------------- FFT-20 (registers, packed f32x2): n=20 --------------
// HZ:   inputs a[5..14] are identically zero (never read).
// CROP: only outputs k in {0..4, 15..19} are produced (a[5..14] left garbage).
template<bool INV, bool HZ, bool CROP>
__device__ __forceinline__ void fft20(float2* a){
    float2 t[20];
    #pragma unroll
    for (int j2=0;j2<5;j2++){
        float2 y0,y1,y2,y3;
        if (HZ){
            float2 x0=a[j2], x3=a[15+j2];
            y0 = add2(x0,x3);
            y2 = sub2(x0,x3);
            if (!INV){ y1 = make_float2(x0.x - x3.y, x0.y + x3.x);
                       y3 = make_float2(x0.x + x3.y, x0.y - x3.x); }
            else     { y1 = make_float2(x0.x + x3.y, x0.y - x3.x);
                       y3 = make_float2(x0.x - x3.y, x0.y + x3.x); }
        } else {
            float2 x0=a[j2], x1=a[5+j2], x2=a[10+j2], x3=a[15+j2];
            float2 s02=add2(x0,x2), d02=sub2(x0,x2);
            float2 s13=add2(x1,x3), d13=sub2(x1,x3);
            y0=add2(s02,s13);
            y2=sub2(s02,s13);
            if (!INV){ y1=make_float2(d02.x+d13.y, d02.y-d13.x);
                       y3=make_float2(d02.x-d13.y, d02.y+d13.x); }
            else     { y1=make_float2(d02.x-d13.y, d02.y+d13.x);
                       y3=make_float2(d02.x+d13.y, d02.y-d13.x); }
        }
        t[j2] = y0;
        if (j2 == 0){               // W^0 == (1,0): skip identity multiplies
            t[5]  = y1;
            t[10] = y2;
            t[15] = y3;
        } else {
            t[5+j2]  = cmul(y1, TW<INV>(20*j2));
            t[10+j2] = cmul(y2, TW<INV>(40*j2));
            t[15+j2] = cmul(y3, TW<INV>(60*j2));
        }
    }
    const float C1f= 0.30901699437494742f, S1f=0.95105651629515357f;
    const float C2f=-0.80901699437494745f, S2f=0.58778525229247313f;
    const float si = INV ? 1.f : -1.f;
    const float2 w1=make_float2(C1f, si*S1f), w2=make_float2(C2f, si*S2f);
    const float2 w3=make_float2(C2f,-si*S2f), w4=make_float2(C1f,-si*S1f);
    ull W1p=F2U(w1), W2p=F2U(w2), W3p=F2U(w3), W4p=F2U(w4);
    ull W1s=F2U(make_float2(w1.y,w1.x)), W2s=F2U(make_float2(w2.y,w2.x));
    ull W3s=F2U(make_float2(w3.y,w3.x)), W4s=F2U(make_float2(w4.y,w4.x));
    #pragma unroll
    for (int k1=0;k1<4;k1++){
        float2 b0=t[k1*5], b1=t[k1*5+1], b2=t[k1*5+2], b3=t[k1*5+3], b4=t[k1*5+4];
        a[k1] = add2(add2(add2(add2(b0,b1),b2),b3),b4);
        if (!CROP){
            ull b1x=pkxx(b1), b1n=pkny(b1);
            ull b2x=pkxx(b2), b2n=pkny(b2);
            ull b3x=pkxx(b3), b3n=pkny(b3);
            ull b4x=pkxx(b4), b4n=pkny(b4);
            float2 y1 = fma2(b1x,W1p, fma2(b1n,W1s, b0));
            y1 = fma2(b2x,W2p, fma2(b2n,W2s, y1));
            y1 = fma2(b3x,W3p, fma2(b3n,W3s, y1));
            y1 = fma2(b4x,W4p, fma2(b4n,W4s, y1));
            a[k1+4]=y1;
            float2 y2 = fma2(b1x,W2p, fma2(b1n,W2s, b0));
            y2 = fma2(b2x,W4p, fma2(b2n,W4s, y2));
            y2 = fma2(b3x,W1p, fma2(b3n,W1s, y2));
            y2 = fma2(b4x,W3p, fma2(b4n,W3s, y2));
            a[k1+8]=y2;
            float2 y3 = fma2(b1x,W3p, fma2(b1n,W3s, b0));
            y3 = fma2(b2x,W1p, fma2(b2n,W1s, y3));
            y3 = fma2(b3x,W4p, fma2(b3n,W4s, y3));
            y3 = fma2(b4x,W2p, fma2(b4n,W2s, y3));
            a[k1+12]=y3;
            float2 y4 = fma2(b1x,W4p, fma2(b1n,W4s, b0));
            y4 = fma2(b2x,W3p, fma2(b2n,W3s, y4));
            y4 = fma2(b3x,W2p, fma2(b3n,W2s, y4));
            y4 = fma2(b4x,W1p, fma2(b4n,W1s, y4));
            a[k1+16]=y4;
        } else {
            if (k1==0){
                float2 y1=b0; y1=cfma(y1,b1,w1); y1=cfma(y1,b2,w2); y1=cfma(y1,b3,w3); y1=cfma(y1,b4,w4);
                a[4]=y1;
            }
            if (k1==3){
                float2 y3=b0; y3=cfma(y3,b1,w3); y3=cfma(y3,b2,w1); y3=cfma(y3,b3,w4); y3=cfma(y3,b4,w2);
                a[15]=y3;
            }
            float2 y4=b0; y4=cfma(y4,b1,w4); y4=cfma(y4,b2,w3); y4=cfma(y4,b3,w2); y4=cfma(y4,b4,w1);
            a[k1+16]=y4;
        }
    }
}

// ----------------------------- FFT-400 (warp, 20 active lanes): 20x20 four-step ----
// PM=0: plain stage-1 loads.
// PM=1: stage-1 load multiplies by pm[idx] (full 400 table; use with HZ=false).
// PM=2: stage-1 load multiplies by phasor pm[map(idx)] (corners; use with HZ=true);
//       if pm==nullptr, multiplies by scalar sc instead.
template<bool INV, bool HZ, bool CROP, int PM>
__device__ void fft400(float2* __restrict__ lin, float2* __restrict__ tmp, int lane,
                       const float2* __restrict__ pm = nullptr, float sc = 1.f){
    __syncwarp();
    float2 r[20];
    if (lane < 20){
        if (HZ){
            #pragma unroll
            for (int j1=0;j1<5;j1++){
                int idx=j1*20+lane;
                float2 v=lin[idx];
                if (PM==2) v = pm ? cmul(v, pm[idx+100]) : make_float2(v.x*sc, v.y*sc);
                r[j1]=v;
            }
            #pragma unroll
            for (int j1=15;j1<20;j1++){
                int idx=j1*20+lane;
                float2 v=lin[idx];
                if (PM==2) v = pm ? cmul(v, pm[idx-300]) : make_float2(v.x*sc, v.y*sc);
                r[j1]=v;
            }
        } else {
            #pragma unroll
            for (int j1=0;j1<20;j1++){
                int idx=j1*20+lane;
                float2 v=lin[idx];
                if (PM==1) v = cmul(v, pm[idx]);
                r[j1]=v;
            }
        }
        fft20<INV,HZ,false>(r);                          // over j1
        // incremental twiddles (scattered loads reduced 19 -> 4)
        float2 Wa = TW<INV>(lane);
        float2 A5 = TW<INV>(5*lane);
        float2 A10= TW<INV>(10*lane);
        float2 A15= TW<INV>(15*lane);
        float2 W2 = cmul(Wa,Wa);
        float2 W3 = cmul(W2,Wa);
        float2 W4 = cmul(W3,Wa);
        r[1]=cmul(r[1],Wa);  r[2]=cmul(r[2],W2);
        r[3]=cmul(r[3],W3);  r[4]=cmul(r[4],W4);
        r[5]=cmul(r[5],A5);
        r[6]=cmul(r[6],cmul(A5,Wa));   r[7]=cmul(r[7],cmul(A5,W2));
        r[8]=cmul(r[8],cmul(A5,W3));   r[9]=cmul(r[9],cmul(A5,W4));
        r[10]=cmul(r[10],A10);
        r[11]=cmul(r[11],cmul(A10,Wa)); r[12]=cmul(r[12],cmul(A10,W2));
        r[13]=cmul(r[13],cmul(A10,W3)); r[14]=cmul(r[14],cmul(A10,W4));
        r[15]=cmul(r[15],A15);
        r[16]=cmul(r[16],cmul(A15,Wa)); r[17]=cmul(r[17],cmul(A15,W2));
        r[18]=cmul(r[18],cmul(A15,W3)); r[19]=cmul(r[19],cmul(A15,W4));
        #pragma unroll
        for (int k1=0;k1<20;k1++) tmp[k1*21+lane]=r[k1];
    }
    __syncwarp();
    if (lane < 20){
        #pragma unroll
        for (int j2=0;j2<20;j2++) r[j2]=tmp[lane*21+j2];
        fft20<INV,false,CROP>(r);                        // over j2
        #pragma unroll
        for (int k2=0;k2<20;k2++)
            if (!CROP || k2<5 || k2>=15) lin[k2*20+lane]=r[k2]; // X[k1+20*k2]
    }
    __syncwarp();
}

#define WPB 4  // warps (transforms) per block for row-FFT kernels

// ----------------------------- init: twiddles + zero histogram -----------------------------
__global__ void kInit(float* out){
    int k = threadIdx.x;
    if (k < 400){
        double ang = -2.0*PI_D*(double)k/400.0;
        g_w400[k] = make_float2((float)cos(ang), (float)sin(ang));
    }
    if (k < 11) out[1250+k] = 0.f;
}

// ----------------------------- precompute layer phasors (pre-scaled by 1/400) ------
__global__ void kPrep(const float* __restrict__ phase){
    int idx = blockIdx.x*256 + threadIdx.x;
    if (idx >= 4*40000) return;
    float p = phase[idx];
    float sv, cv;
    sincospif(2.f*(sinf(p)+1.f), &sv, &cv);   // e^{i*2*pi*(sin(p)+1)}
    const float sc = 1.f/400.f;
    g_PH[idx] = make_float2(cv*sc, sv*sc);
}

// ----------------------------- transpose transfer functions (pre-scaled by 1/400) --
__global__ void kHT(const float2* __restrict__ t0, const float2* __restrict__ t1,
                    const float2* __restrict__ t2){
    __shared__ float2 tile[32][33];
    int m = blockIdx.z;
    const float2* src = (m==0)? t0 : (m==1)? t1 : t2;
    int r0 = blockIdx.y*32, k0 = blockIdx.x*32;
    int tx = threadIdx.x, ty = threadIdx.y;   // 32 x 8
    const float sc = 1.f/400.f;
    for (int yy=ty; yy<32; yy+=8){
        int r = r0+yy, k = k0+tx;
        if (r<400 && k<400) tile[yy][tx] = src[r*400+k];
    }
    __syncthreads();
    for (int yy=ty; yy<32; yy+=8){
        int k = k0+yy, r = r0+tx;
        if (r<400 && k<400){
            float2 v = tile[tx][yy];
            g_HT[(size_t)m*160000 + k*400 + r] = make_float2(v.x*sc, v.y*sc);
        }
    }
}

// ----------------------------- W1 transpose (tiled) + row sums -----------------------------
__global__ void kT(const float* __restrict__ W1){
    __shared__ float tile[32][33];
    int p0 = blockIdx.x*32, h0 = blockIdx.y*32;
    int tx = threadIdx.x, ty = threadIdx.y;   // 32 x 8
    for (int yy=ty; yy<32; yy+=8){
        int hh = h0+yy, p = p0+tx;
        if (hh<512 && p<625) tile[yy][tx] = W1[hh*625+p];
    }
    __syncthreads();
    for (int yy=ty; yy<32; yy+=8){
        int p = p0+yy, hh = h0+tx;
        if (p<625 && hh<512) g_W1T[p*512+hh] = tile[tx][yy];
    }
}
__global__ void kR1(const float* __restrict__ W1){   // grid 512, block 128
    __shared__ float red[128];
    int hh = blockIdx.x, tid = threadIdx.x;
    float s = 0.f;
    for (int p=tid; p<625; p+=128) s += W1[hh*625+p];
    red[tid] = s;
    __syncthreads();
    for (int st=64; st>0; st>>=1){
        if (tid<st) red[tid]+=red[tid+st];
        __syncthreads();
    }
    if (tid==0) g_R1[hh] = red[0];
}

// ----------------------------- A0: real input, 2 rows packed per complex FFT --------
__global__ void kA0(const float* __restrict__ x){   // grid 800, block 128
    __shared__ __align__(16) float2 s_lin[WPB][400];
    __shared__ float2 s_tmp[WPB][421];
    int w = threadIdx.x>>5, lane = threadIdx.x&31;
    int idx = blockIdx.x*WPB + w;                   // 0..3199 row-pairs
    int b = idx/100, pr = idx%100;
    int c0 = 2*pr, c1 = 2*pr+1;
    int i0 = (c0<100)? c0+100 : c0-100;             // logical rows
    int i1 = (c1<100)? c1+100 : c1-100;
    const float4* x0r4 = (const float4*)(x + ((size_t)b*200 + i0)*200);
    const float4* x1r4 = (const float4*)(x + ((size_t)b*200 + i1)*200);
    float2* lin = s_lin[w]; float2* tmp = s_tmp[w];
    if (lane < 25){
        float4 a0 = x0r4[25+lane], b0 = x1r4[25+lane];   // x[100..199] -> lin[0..99]
        lin[4*lane  ] = make_float2(a0.x, b0.x);
        lin[4*lane+1] = make_float2(a0.y, b0.y);
        lin[4*lane+2] = make_float2(a0.z, b0.z);
        lin[4*lane+3] = make_float2(a0.w, b0.w);
        float4 a1 = x0r4[lane],    b1 = x1r4[lane];      // x[0..99] -> lin[300..399]
        lin[300+4*lane  ] = make_float2(a1.x, b1.x);
        lin[300+4*lane+1] = make_float2(a1.y, b1.y);
        lin[300+4*lane+2] = make_float2(a1.z, b1.z);
        lin[300+4*lane+3] = make_float2(a1.w, b1.w);
    }
    fft400<false,true,false,0>(lin,tmp,lane);
    float2* row0 = g_S + ((size_t)b*200+c0)*400;
    float2* row1 = g_S + ((size_t)b*200+c1)*400;
    for (int k=lane; k<400; k+=32){
        float2 Zk = lin[k];
        float2 Zr = lin[(400-k) & 399];   // (400-k)%400; k=0 -> 0
        row0[k] = make_float2(0.5f*(Zk.x+Zr.x),  0.5f*(Zk.y-Zr.y));
        row1[k] = make_float2(0.5f*(Zk.y+Zr.y), -0.5f*(Zk.x-Zr.x));
    }
}

// ----------------------------- B (warp-private): col FFT * trans * col IFFT --------
__global__ void __launch_bounds__(128) kB(int hm){
    __shared__ __align__(16) float2 colb[8][401];
    __shared__ float2 tmpb[4][421];
    int b  = blockIdx.x / 50;
    int k0 = (blockIdx.x % 50) * 8;
    int tid = threadIdx.x;
    const float4* Sb4 = (const float4*)(g_S + (size_t)b*200*400);
    const float2* HT = g_HT + (size_t)hm*160000;

    // stage in (float4 = 2 complex): col[kl][r], r in [0,100) U [300,400)
    for (int idx=tid; idx<800; idx+=128){
        int c = idx>>2, q = idx&3;
        float4 v = Sb4[c*200 + (k0>>1) + q];
        int r = (c<100)? c : c+200;
        colb[2*q  ][r] = make_float2(v.x,v.y);
        colb[2*q+1][r] = make_float2(v.z,v.w);
    }
    __syncthreads();

    int w = tid>>5, lane = tid&31;
    float2* colA = colb[2*w];
    float2* colB = colb[2*w+1];
    fft400<false,true,false,0>(colA, tmpb[w], lane);              // A fwd
    fft400<false,true,false,0>(colB, tmpb[w], lane);              // B fwd
    fft400<true,false,true,1>(colA, tmpb[w], lane,
                              HT + (size_t)(k0+2*w)*400);         // A inv, fused *H
    fft400<true,false,true,1>(colB, tmpb[w], lane,
                              HT + (size_t)(k0+2*w+1)*400);       // B inv, fused *H
    __syncthreads();

    // stage out (float4), crop rows (no scale: folded into HT)
    float4* S2b4 = (float4*)(g_S2 + (size_t)b*200*400);
    for (int idx=tid; idx<800; idx+=128){
        int c = idx>>2, q = idx&3;
        int r = (c<100)? c : c+200;
        float2 v0 = colb[2*q  ][r];
        float2 v1 = colb[2*q+1][r];
        S2b4[c*200 + (k0>>1) + q] = make_float4(v0.x, v0.y, v1.x, v1.y);
    }
}

// ----------------------------- C: row IFFT + phasor + row FFT (fully fused) --------
__global__ void kC(int l){   // l < 0: no phasor (first boundary)
    __shared__ __align__(16) float2 s_lin[WPB][400];
    __shared__ float2 s_tmp[WPB][421];
    int w = threadIdx.x>>5, lane = threadIdx.x&31;
    int idx = blockIdx.x*WPB + w;
    int b = idx/200, c = idx%200;
    float2* lin = s_lin[w]; float2* tmp = s_tmp[w];
    const float4* S4 = (const float4*)(g_S2 + ((size_t)b*200+c)*400);
    float4* lin4 = (float4*)lin;
    for (int m4=lane;m4<200;m4+=32) lin4[m4]=S4[m4];
    fft400<true,false,true,0>(lin,tmp,lane);        // cropped inverse (corners valid)
    int i = (c<100)? c+100 : c-100;                 // logical row
    const float2* phrow = (l>=0)? (g_PH + (size_t)l*40000 + i*200) : nullptr;
    // forward FFT with phasor (pre-scaled 1/400) fused into stage-1 corner loads
    fft400<false,true,false,2>(lin,tmp,lane, phrow, 1.f/400.f);
    float4* out4 = (float4*)(g_S + ((size_t)b*200+c)*400);
    const float4* l4 = (const float4*)lin;
    for (int m4=lane;m4<200;m4+=32) out4[m4]=l4[m4];
}

// ----------------------------- CF: row IFFT -> intensity -> horizontal 8-sums ------
__global__ void kCF(){
    __shared__ __align__(16) float2 s_lin[WPB][400];
    __shared__ float2 s_tmp[WPB][421];
    int w = threadIdx.x>>5, lane = threadIdx.x&31;
    int idx = blockIdx.x*WPB + w;
    int b = idx/200, c = idx%200;
    float2* lin = s_lin[w]; float2* tmp = s_tmp[w];
    const float4* S4 = (const float4*)(g_S2 + ((size_t)b*200+c)*400);
    float4* lin4 = (float4*)lin;
    for (int m4=lane;m4<200;m4+=32) lin4[m4]=S4[m4];
    fft400<true,false,true,0>(lin,tmp,lane);        // cropped inverse
    int i = (c<100)? c+100 : c-100;
    float* pbuf = (float*)tmp;                      // tmp is free now; 200 floats
    const float sc = 1.f/400.f;
    for (int cc=lane;cc<200;cc+=32){
        int rc = (cc<100)? cc : cc+200;
        int j  = (cc<100)? cc+100 : cc-100;
        float vx = lin[rc].x*sc, vy = lin[rc].y*sc;
        pbuf[j] = vx*vx + vy*vy;
    }
    __syncwarp();
    if (lane < 25){
        float s = 0.f;
        #pragma unroll
        for (int v=0; v<8; v++) s += pbuf[lane*8+v];
        g_Pp[((size_t)b*200+i)*25 + lane] = s;
    }
}

// ----------------------------- pooling: vertical sum of 8 partials -> [p][b] -------
__global__ void kPool(){
    int idx = blockIdx.x*256 + threadIdx.x;
    if (idx >= 20000) return;
    int b = idx / 625, p = idx % 625;
    int mi = p/25, mj = p%25;
    const float* base = g_Pp + ((size_t)b*200 + mi*8)*25 + mj;
    float s = 0.f;
    #pragma unroll
    for (int u=0;u<8;u++) s += base[u*25];
    g_pool[p*32+b] = s*(1.f/64.f);
}

// ----------------------------- per-window MLP + voting -----------------------------
#define HSTR 513    // padded hid stride (bank-conflict-free)
__global__ void __launch_bounds__(256) kWin(
                     const float* __restrict__ b1, const float* __restrict__ W2,
                     const float* __restrict__ b2, const float* __restrict__ gamma,
                     const float* __restrict__ beta, float* __restrict__ out)
{
    extern __shared__ float dsm[];
    float* swin = dsm;                    // [cell][b] up to 25*32
    float* hid  = dsm + 800;              // [b][hh] 32*HSTR
    float* lg   = dsm + 800 + 32*HSTR;    // [b][o]  32*10
    __shared__ double red1[256], red2[256];
    __shared__ int   pidx[25];
    __shared__ float s_inv, s_c0;
    __shared__ int   s_a[32];
    __shared__ float s_delta[32];

    int wI = blockIdx.x;
    int i = wI/25, j = wI%25;
    int wr = min(5, 25-i), wc = min(5, 25-j);
    int cells = wr*wc;
    int tid = threadIdx.x;
    if (tid < cells) pidx[tid] = (i + tid/wc)*25 + (j + tid%wc);
    __syncthreads();

    double s1 = 0.0, s2 = 0.0;
    for (int q=tid; q<cells*32; q+=256){
        int cell = q>>5, b = q&31;
        float v = g_pool[pidx[cell]*32 + b];
        swin[q] = v;
        s1 += v; s2 += (double)v*(double)v;
    }
    red1[tid]=s1; red2[tid]=s2;
    __syncthreads();
    for (int st=128; st>0; st>>=1){
        if (tid<st){ red1[tid]+=red1[tid+st]; red2[tid]+=red2[tid+st]; }
        __syncthreads();
    }
    if (tid == 0){
        double mu  = red1[0]/20000.0;
        double var = red2[0]/20000.0 - mu*mu;
        float inv = gamma[0]/(float)sqrt(var + 1e-5);
        s_inv = inv;
        s_c0  = beta[0] - (float)mu*inv;
    }
    __syncthreads();
    float inv = s_inv, c0 = s_c0;

    // hid[b][hh] = relu(c0*R1 + inv*<win,W1win> + b1); 8 batches per thread.
    for (int it=0; it<8; it++){
        int task = it*256 + tid;          // 2048 tasks = 4 bgroups x 512 hh
        int hh = task & 511, bg = task >> 9;
        float acc[8];
        #pragma unroll
        for (int u=0;u<8;u++) acc[u]=0.f;
        for (int cell=0; cell<cells; cell++){
            float wv = g_W1T[pidx[cell]*512+hh];
            const float* sw = swin + cell*32 + bg*8;
            #pragma unroll
            for (int u=0;u<8;u++) acc[u] = fmaf(sw[u], wv, acc[u]);
        }
        float base = fmaf(c0, g_R1[hh], b1[hh]);
        #pragma unroll
        for (int u=0;u<8;u++){
            float pre = fmaf(inv, acc[u], base);
            hid[(bg*8+u)*HSTR + hh] = fmaxf(pre, 0.f);
        }
    }
    __syncthreads();

    for (int t=tid; t<320; t+=256){
        int b = t/10, oo = t%10;
        float acc = b2[oo];
        const float* hb = hid + b*HSTR;
        const float* wv = W2 + oo*512;
        for (int hh=0; hh<512; hh++) acc = fmaf(hb[hh], wv[hh], acc);
        lg[b*10+oo] = acc;
    }
    __syncthreads();

    if (tid < 32){
        int b = tid;
        float lmax = lg[b*10], lmin = lg[b*10];
        int am = 0;
        for (int oo=1;oo<10;oo++){
            float v = lg[b*10+oo];
            if (v > lmax){ lmax = v; am = oo; }
            if (v < lmin)  lmin = v;
        }
        float se = 0.f;
        for (int oo=0;oo<10;oo++) se += expf(lg[b*10+oo]-lmax);
        s_a[b] = am;
        s_delta[b] = (1.f - expf(lmin-lmax))/se;  // pmax - pmin
    }
    __syncthreads();
    if (tid == 0){
        int votes[11];
        for (int k=0;k<11;k++) votes[k]=0;
        for (int b=0;b<32;b++) votes[s_a[b]]++;
        int f0 = 0, best = votes[0];
        for (int k=1;k<11;k++) if (votes[k] > best){ best = votes[k]; f0 = k; }
        float sum = 0.f; int cnt = 0;
        for (int b=0;b<32;b++)
            if (s_a[b]==f0 && s_delta[b]!=0.f){ sum += s_delta[b]; cnt++; }
        int fin;
        if (cnt > 0){ float d1 = sum/(float)cnt; fin = (d1 < 0.2f) ? 0 : f0+1; }
        else fin = f0+1;   // delta1 = NaN; NaN < THR is false
        out[wI]       = (fin==0) ? 0.f : (float)fin;
        out[625+wI]   = (fin!=0) ? 1.f : 0.f;
        atomicAdd(&out[1250+fin], 1.0f);   // exact integer counts -> deterministic
    }
}

// ----------------------------- launch -----------------------------
extern "C" void kernel_launch(void* const* d_in, const int* in_sizes, int n_in,
                              void* d_out, int out_size)
{
    int o = (n_in >= 12 && in_sizes[1] == 1) ? 1 : 0;  // skip batch_size scalar if present
    const float*  x     = (const float*) d_in[0];
    const float2* h     = (const float2*)d_in[1+o];
    const float2* h_pro = (const float2*)d_in[2+o];
    const float2* h_det = (const float2*)d_in[3+o];
    const float*  phase = (const float*) d_in[4+o];
    const float*  W1    = (const float*) d_in[5+o];
    const float*  b1    = (const float*) d_in[6+o];
    const float*  W2    = (const float*) d_in[7+o];
    const float*  b2    = (const float*) d_in[8+o];
    const float*  gamma = (const float*) d_in[9+o];
    const float*  beta  = (const float*) d_in[10+o];
    float* out = (float*)d_out;

    cudaFuncSetAttribute(kWin, cudaFuncAttributeMaxDynamicSharedMemorySize,
                         (800 + 32*HSTR + 320)*4);

    kInit<<<1,512>>>(out);
    kPrep<<<625,256>>>(phase);
    kHT <<<dim3(13,13,3),dim3(32,8)>>>(h_pro, h, h_det);   // [0]=h_pro, [1]=h, [2]=h_det
    kT  <<<dim3(20,16),dim3(32,8)>>>(W1);
    kR1 <<<512,128>>>(W1);

    kA0 <<<800,128>>>(x);                  // 2 rows per FFT (real packing)
    kB  <<<1600,128>>>(0);                 // h_pro
    kC  <<<1600,128>>>(-1);
    for (int l=0; l<4; l++){
        kB <<<1600,128>>>(1);              // h (transposed once, reused 4x)
        kC <<<1600,128>>>(l);
    }
    kB  <<<1600,128>>>(2);                 // h_det
    kCF <<<1600,128>>>();

    kPool<<<79,256>>>();

    kWin<<<625,256,(800 + 32*HSTR + 320)*4>>>(b1, W2, b2, gamma, beta, out);
}

// round 12
// speedup vs baseline: 1.1344x; 1.0290x over previous
#include <cuda_runtime.h>
#include <math.h>

#define PI_D 3.14159265358979323846
typedef unsigned long long ull;

// ----------------------------- scratch (device globals) -----------------------------
__device__ __align__(16) float2 g_S [32*200*400];   // row-FFT'd field, compact rows
__device__ __align__(16) float2 g_S2[32*200*400];   // after col FFT * trans * IFFT
__device__ float2 g_HT[3*400*400];    // transposed transfer functions [m][k][r], pre-scaled 1/400
__device__ float2 g_PH[4*200*200];    // precomputed layer phasors [l][i][j], pre-scaled 1/400
__device__ float  g_Pp[32*200*25];    // horizontal 8-sums of intensity [b][i][j8]
__device__ float  g_pool[625*32];     // pooled [p][b]
__device__ float  g_W1T[625*512];     // W1 transposed [p][hh]
__device__ float  g_R1[512];          // row sums of W1
__device__ float2 g_w400[400];        // e^{-2*pi*i*k/400}, fp64-initialized

// ----------------------------- packed f32x2 helpers (sm_100+) -----------------------
__device__ __forceinline__ ull F2U(float2 v){
    ull r; asm("mov.b64 %0, {%1,%2};" : "=l"(r) : "f"(v.x), "f"(v.y)); return r;
}
__device__ __forceinline__ float2 U2F(ull v){
    float2 r; asm("mov.b64 {%0,%1}, %2;" : "=f"(r.x), "=f"(r.y) : "l"(v)); return r;
}
__device__ __forceinline__ float2 add2(float2 a, float2 b){
    ull r; asm("add.rn.f32x2 %0, %1, %2;" : "=l"(r) : "l"(F2U(a)), "l"(F2U(b)));
    return U2F(r);
}
__device__ __forceinline__ float2 sub2(float2 a, float2 b){   // a - b == fma(b,-1,a), exact
    const ull N1 = 0xBF800000BF800000ULL;
    ull r; asm("fma.rn.f32x2 %0, %1, %2, %3;" : "=l"(r) : "l"(F2U(b)), "l"(N1), "l"(F2U(a)));
    return U2F(r);
}
__device__ __forceinline__ float2 fma2(ull a, ull b, float2 c){
    ull r; asm("fma.rn.f32x2 %0, %1, %2, %3;" : "=l"(r) : "l"(a), "l"(b), "l"(F2U(c)));
    return U2F(r);
}
__device__ __forceinline__ ull pkxx(float2 a){
    ull r; asm("mov.b64 %0, {%1,%2};" : "=l"(r) : "f"(a.x), "f"(a.x)); return r;
}
__device__ __forceinline__ ull pkny(float2 a){
    ull r; asm("mov.b64 %0, {%1,%2};" : "=l"(r) : "f"(-a.y), "f"(a.y)); return r;
}

// ----------------------------- complex helpers -----------------------------
__device__ __forceinline__ float2 cmul(float2 a, float2 b){
    return make_float2(fmaf(a.x,b.x,-a.y*b.y), fmaf(a.x,b.y, a.y*b.x));
}
__device__ __forceinline__ float2 cfma(float2 r, float2 a, float2 w){
    r.x = fmaf(a.x,w.x, fmaf(-a.y,w.y,r.x));
    r.y = fmaf(a.x,w.y, fmaf( a.y,w.x,r.y));
    return r;
}
template<bool INV>
__device__ __forceinline__ float2 TW(int m){   // W400^m (conj if INV)
    float2 v = g_w400[m];
    if (INV) v.y = -v.y;
    return v;
}

// ----------------------------- FFT-20 (registers, packed f32x2): n=20 --------------
// HZ:   inputs a[5..14] are identically zero (never read).
// CROP: only outputs k in {0..4, 15..19} are produced (a[5..14] left garbage).
template<bool INV, bool HZ, bool CROP>
__device__ __forceinline__ void fft20(float2* a){
    float2 t[20];
    #pragma unroll
    for (int j2=0;j2<5;j2++){
        float2 y0,y1,y2,y3;
        if (HZ){
            float2 x0=a[j2], x3=a[15+j2];
            y0 = add2(x0,x3);
            y2 = sub2(x0,x3);
            if (!INV){ y1 = make_float2(x0.x - x3.y, x0.y + x3.x);
                       y3 = make_float2(x0.x + x3.y, x0.y - x3.x); }
            else     { y1 = make_float2(x0.x + x3.y, x0.y - x3.x);
                       y3 = make_float2(x0.x - x3.y, x0.y + x3.x); }
        } else {
            float2 x0=a[j2], x1=a[5+j2], x2=a[10+j2], x3=a[15+j2];
            float2 s02=add2(x0,x2), d02=sub2(x0,x2);
            float2 s13=add2(x1,x3), d13=sub2(x1,x3);
            y0=add2(s02,s13);
            y2=sub2(s02,s13);
            if (!INV){ y1=make_float2(d02.x+d13.y, d02.y-d13.x);
                       y3=make_float2(d02.x-d13.y, d02.y+d13.x); }
            else     { y1=make_float2(d02.x-d13.y, d02.y+d13.x);
                       y3=make_float2(d02.x+d13.y, d02.y-d13.x); }
        }
        t[j2] = y0;
        if (j2 == 0){               // W^0 == (1,0): skip identity multiplies
            t[5]  = y1;
            t[10] = y2;
            t[15] = y3;
        } else {
            t[5+j2]  = cmul(y1, TW<INV>(20*j2));
            t[10+j2] = cmul(y2, TW<INV>(40*j2));
            t[15+j2] = cmul(y3, TW<INV>(60*j2));
        }
    }
    const float C1f= 0.30901699437494742f, S1f=0.95105651629515357f;
    const float C2f=-0.80901699437494745f, S2f=0.58778525229247313f;
    const float si = INV ? 1.f : -1.f;
    const float2 w1=make_float2(C1f, si*S1f), w2=make_float2(C2f, si*S2f);
    const float2 w3=make_float2(C2f,-si*S2f), w4=make_float2(C1f,-si*S1f);
    ull W1p=F2U(w1), W2p=F2U(w2), W3p=F2U(w3), W4p=F2U(w4);
    ull W1s=F2U(make_float2(w1.y,w1.x)), W2s=F2U(make_float2(w2.y,w2.x));
    ull W3s=F2U(make_float2(w3.y,w3.x)), W4s=F2U(make_float2(w4.y,w4.x));
    #pragma unroll
    for (int k1=0;k1<4;k1++){
        float2 b0=t[k1*5], b1=t[k1*5+1], b2=t[k1*5+2], b3=t[k1*5+3], b4=t[k1*5+4];
        a[k1] = add2(add2(add2(add2(b0,b1),b2),b3),b4);
        if (!CROP){
            ull b1x=pkxx(b1), b1n=pkny(b1);
            ull b2x=pkxx(b2), b2n=pkny(b2);
            ull b3x=pkxx(b3), b3n=pkny(b3);
            ull b4x=pkxx(b4), b4n=pkny(b4);
            float2 y1 = fma2(b1x,W1p, fma2(b1n,W1s, b0));
            y1 = fma2(b2x,W2p, fma2(b2n,W2s, y1));
            y1 = fma2(b3x,W3p, fma2(b3n,W3s, y1));
            y1 = fma2(b4x,W4p, fma2(b4n,W4s, y1));
            a[k1+4]=y1;
            float2 y2 = fma2(b1x,W2p, fma2(b1n,W2s, b0));
            y2 = fma2(b2x,W4p, fma2(b2n,W4s, y2));
            y2 = fma2(b3x,W1p, fma2(b3n,W1s, y2));
            y2 = fma2(b4x,W3p, fma2(b4n,W3s, y2));
            a[k1+8]=y2;
            float2 y3 = fma2(b1x,W3p, fma2(b1n,W3s, b0));
            y3 = fma2(b2x,W1p, fma2(b2n,W1s, y3));
            y3 = fma2(b3x,W4p, fma2(b3n,W4s, y3));
            y3 = fma2(b4x,W2p, fma2(b4n,W2s, y3));
            a[k1+12]=y3;
            float2 y4 = fma2(b1x,W4p, fma2(b1n,W4s, b0));
            y4 = fma2(b2x,W3p, fma2(b2n,W3s, y4));
            y4 = fma2(b3x,W2p, fma2(b3n,W2s, y4));
            y4 = fma2(b4x,W1p, fma2(b4n,W1s, y4));
            a[k1+16]=y4;
        } else {
            if (k1==0){
                float2 y1=b0; y1=cfma(y1,b1,w1); y1=cfma(y1,b2,w2); y1=cfma(y1,b3,w3); y1=cfma(y1,b4,w4);
                a[4]=y1;
            }
            if (k1==3){
                float2 y3=b0; y3=cfma(y3,b1,w3); y3=cfma(y3,b2,w1); y3=cfma(y3,b3,w4); y3=cfma(y3,b4,w2);
                a[15]=y3;
            }
            float2 y4=b0; y4=cfma(y4,b1,w4); y4=cfma(y4,b2,w3); y4=cfma(y4,b3,w2); y4=cfma(y4,b4,w1);
            a[k1+16]=y4;
        }
    }
}

// ----------------------------- incremental inter-stage twiddles --------------------
template<bool INV>
__device__ __forceinline__ void twiddle_apply(float2* r, int lane){
    float2 Wa = TW<INV>(lane);
    float2 A5 = TW<INV>(5*lane);
    float2 A10= TW<INV>(10*lane);
    float2 A15= TW<INV>(15*lane);
    float2 W2 = cmul(Wa,Wa);
    float2 W3 = cmul(W2,Wa);
    float2 W4 = cmul(W3,Wa);
    r[1]=cmul(r[1],Wa);  r[2]=cmul(r[2],W2);
    r[3]=cmul(r[3],W3);  r[4]=cmul(r[4],W4);
    r[5]=cmul(r[5],A5);
    r[6]=cmul(r[6],cmul(A5,Wa));   r[7]=cmul(r[7],cmul(A5,W2));
    r[8]=cmul(r[8],cmul(A5,W3));   r[9]=cmul(r[9],cmul(A5,W4));
    r[10]=cmul(r[10],A10);
    r[11]=cmul(r[11],cmul(A10,Wa)); r[12]=cmul(r[12],cmul(A10,W2));
    r[13]=cmul(r[13],cmul(A10,W3)); r[14]=cmul(r[14],cmul(A10,W4));
    r[15]=cmul(r[15],A15);
    r[16]=cmul(r[16],cmul(A15,Wa)); r[17]=cmul(r[17],cmul(A15,W2));
    r[18]=cmul(r[18],cmul(A15,W3)); r[19]=cmul(r[19],cmul(A15,W4));
}

// ----------------------------- FFT-400 (warp, 20 active lanes): 20x20 four-step ----
// (generic version kept for kA0 / kCF)
template<bool INV, bool HZ, bool CROP>
__device__ void fft400(float2* __restrict__ lin, float2* __restrict__ tmp, int lane){
    __syncwarp();
    float2 r[20];
    if (lane < 20){
        if (HZ){
            #pragma unroll
            for (int j1=0;j1<5;j1++)  r[j1]=lin[j1*20+lane];
            #pragma unroll
            for (int j1=15;j1<20;j1++) r[j1]=lin[j1*20+lane];
        } else {
            #pragma unroll
            for (int j1=0;j1<20;j1++) r[j1]=lin[j1*20+lane];
        }
        fft20<INV,HZ,false>(r);
        twiddle_apply<INV>(r,lane);
        #pragma unroll
        for (int k1=0;k1<20;k1++) tmp[k1*21+lane]=r[k1];
    }
    __syncwarp();
    if (lane < 20){
        #pragma unroll
        for (int j2=0;j2<20;j2++) r[j2]=tmp[lane*21+j2];
        fft20<INV,false,CROP>(r);
        #pragma unroll
        for (int k2=0;k2<20;k2++)
            if (!CROP || k2<5 || k2>=15) lin[k2*20+lane]=r[k2];
    }
    __syncwarp();
}

// ----------------------------- kB fused transform: fwd FFT -> *H -> inv FFT --------
// Position identity p=20*k2+k1 == freq index k1+20*k2: fwd-stage2 output in lane L
// occupies exactly the positions {20m+L} that inv-stage1 lane L reads -> the middle
// smem round trip stays in registers.
__device__ void fftB_fused(float2* __restrict__ col, float2* __restrict__ tmp,
                           int lane, const float2* __restrict__ ht){
    __syncwarp();
    float2 r[20];
    if (lane < 20){
        #pragma unroll
        for (int j1=0;j1<5;j1++)  r[j1]=col[j1*20+lane];
        #pragma unroll
        for (int j1=15;j1<20;j1++) r[j1]=col[j1*20+lane];
        fft20<false,true,false>(r);          // fwd stage1 (half-zero)
        twiddle_apply<false>(r,lane);
        #pragma unroll
        for (int k1=0;k1<20;k1++) tmp[k1*21+lane]=r[k1];
    }
    __syncwarp();
    if (lane < 20){
        #pragma unroll
        for (int j2=0;j2<20;j2++) r[j2]=tmp[lane*21+j2];
    }
    __syncwarp();                            // tmp reads done before overwrite
    if (lane < 20){
        fft20<false,false,false>(r);         // fwd stage2 -> X at pos 20m+lane
        #pragma unroll
        for (int j1=0;j1<20;j1++) r[j1]=cmul(r[j1], ht[j1*20+lane]);  // *H (pre-scaled)
        fft20<true,false,false>(r);          // inv stage1
        twiddle_apply<true>(r,lane);
        #pragma unroll
        for (int k1=0;k1<20;k1++) tmp[k1*21+lane]=r[k1];
    }
    __syncwarp();
    if (lane < 20){
        #pragma unroll
        for (int j2=0;j2<20;j2++) r[j2]=tmp[lane*21+j2];
        fft20<true,false,true>(r);           // inv stage2, cropped
        #pragma unroll
        for (int k2=0;k2<20;k2++)
            if (k2<5 || k2>=15) col[k2*20+lane]=r[k2];
    }
    __syncwarp();
}

// ----------------------------- kC fused transform: inv FFT -> phasor -> fwd FFT ----
// inv-stage2 corner outputs (pos 20*k2+lane) are exactly fwd-stage1's HZ inputs in
// the same lane -> phasor multiply happens in registers, no middle smem pass.
__device__ void fftC_fused(float2* __restrict__ lin, float2* __restrict__ tmp,
                           int lane, const float2* __restrict__ ph){
    __syncwarp();
    float2 r[20];
    if (lane < 20){
        #pragma unroll
        for (int j1=0;j1<20;j1++) r[j1]=lin[j1*20+lane];
        fft20<true,false,false>(r);          // inv stage1
        twiddle_apply<true>(r,lane);
        #pragma unroll
        for (int k1=0;k1<20;k1++) tmp[k1*21+lane]=r[k1];
    }
    __syncwarp();
    if (lane < 20){
        #pragma unroll
        for (int j2=0;j2<20;j2++) r[j2]=tmp[lane*21+j2];
    }
    __syncwarp();                            // tmp reads done before overwrite
    if (lane < 20){
        fft20<true,false,true>(r);           // inv stage2 CROP: corners valid
        if (ph){
            #pragma unroll
            for (int k2=0;k2<5;k2++)   r[k2] = cmul(r[k2], ph[20*k2+lane+100]);
            #pragma unroll
            for (int k2=15;k2<20;k2++) r[k2] = cmul(r[k2], ph[20*k2+lane-300]);
        } else {
            const float sc = 1.f/400.f;
            #pragma unroll
            for (int k2=0;k2<5;k2++){  r[k2].x*=sc; r[k2].y*=sc; }
            #pragma unroll
            for (int k2=15;k2<20;k2++){ r[k2].x*=sc; r[k2].y*=sc; }
        }
        fft20<false,true,false>(r);          // fwd stage1 (half-zero corners)
        twiddle_apply<false>(r,lane);
        #pragma unroll
        for (int k1=0;k1<20;k1++) tmp[k1*21+lane]=r[k1];
    }
    __syncwarp();
    if (lane < 20){
        #pragma unroll
        for (int j2=0;j2<20;j2++) r[j2]=tmp[lane*21+j2];
        fft20<false,false,false>(r);         // fwd stage2
        #pragma unroll
        for (int k2=0;k2<20;k2++) lin[k2*20+lane]=r[k2];
    }
    __syncwarp();
}

#define WPB 4  // warps (transforms) per block for row-FFT kernels

// ----------------------------- init: twiddles + zero histogram -----------------------------
__global__ void kInit(float* out){
    int k = threadIdx.x;
    if (k < 400){
        double ang = -2.0*PI_D*(double)k/400.0;
        g_w400[k] = make_float2((float)cos(ang), (float)sin(ang));
    }
    if (k < 11) out[1250+k] = 0.f;
}

// ----------------------------- precompute layer phasors (pre-scaled by 1/400) ------
__global__ void kPrep(const float* __restrict__ phase){
    int idx = blockIdx.x*256 + threadIdx.x;
    if (idx >= 4*40000) return;
    float p = phase[idx];
    float sv, cv;
    sincospif(2.f*(sinf(p)+1.f), &sv, &cv);   // e^{i*2*pi*(sin(p)+1)}
    const float sc = 1.f/400.f;
    g_PH[idx] = make_float2(cv*sc, sv*sc);
}

// ----------------------------- transpose transfer functions (pre-scaled by 1/400) --
__global__ void kHT(const float2* __restrict__ t0, const float2* __restrict__ t1,
                    const float2* __restrict__ t2){
    __shared__ float2 tile[32][33];
    int m = blockIdx.z;
    const float2* src = (m==0)? t0 : (m==1)? t1 : t2;
    int r0 = blockIdx.y*32, k0 = blockIdx.x*32;
    int tx = threadIdx.x, ty = threadIdx.y;   // 32 x 8
    const float sc = 1.f/400.f;
    for (int yy=ty; yy<32; yy+=8){
        int r = r0+yy, k = k0+tx;
        if (r<400 && k<400) tile[yy][tx] = src[r*400+k];
    }
    __syncthreads();
    for (int yy=ty; yy<32; yy+=8){
        int k = k0+yy, r = r0+tx;
        if (r<400 && k<400){
            float2 v = tile[tx][yy];
            g_HT[(size_t)m*160000 + k*400 + r] = make_float2(v.x*sc, v.y*sc);
        }
    }
}

// ----------------------------- W1 transpose (tiled) + row sums -----------------------------
__global__ void kT(const float* __restrict__ W1){
    __shared__ float tile[32][33];
    int p0 = blockIdx.x*32, h0 = blockIdx.y*32;
    int tx = threadIdx.x, ty = threadIdx.y;   // 32 x 8
    for (int yy=ty; yy<32; yy+=8){
        int hh = h0+yy, p = p0+tx;
        if (hh<512 && p<625) tile[yy][tx] = W1[hh*625+p];
    }
    __syncthreads();
    for (int yy=ty; yy<32; yy+=8){
        int p = p0+yy, hh = h0+tx;
        if (p<625 && hh<512) g_W1T[p*512+hh] = tile[tx][yy];
    }
}
__global__ void kR1(const float* __restrict__ W1){   // grid 512, block 128
    __shared__ float red[128];
    int hh = blockIdx.x, tid = threadIdx.x;
    float s = 0.f;
    for (int p=tid; p<625; p+=128) s += W1[hh*625+p];
    red[tid] = s;
    __syncthreads();
    for (int st=64; st>0; st>>=1){
        if (tid<st) red[tid]+=red[tid+st];
        __syncthreads();
    }
    if (tid==0) g_R1[hh] = red[0];
}

// ----------------------------- A0: real input, 2 rows packed per complex FFT --------
__global__ void kA0(const float* __restrict__ x){   // grid 800, block 128
    __shared__ __align__(16) float2 s_lin[WPB][400];
    __shared__ float2 s_tmp[WPB][421];
    int w = threadIdx.x>>5, lane = threadIdx.x&31;
    int idx = blockIdx.x*WPB + w;                   // 0..3199 row-pairs
    int b = idx/100, pr = idx%100;
    int c0 = 2*pr, c1 = 2*pr+1;
    int i0 = (c0<100)? c0+100 : c0-100;             // logical rows
    int i1 = (c1<100)? c1+100 : c1-100;
    const float4* x0r4 = (const float4*)(x + ((size_t)b*200 + i0)*200);
    const float4* x1r4 = (const float4*)(x + ((size_t)b*200 + i1)*200);
    float2* lin = s_lin[w]; float2* tmp = s_tmp[w];
    if (lane < 25){
        float4 a0 = x0r4[25+lane], b0 = x1r4[25+lane];   // x[100..199] -> lin[0..99]
        lin[4*lane  ] = make_float2(a0.x, b0.x);
        lin[4*lane+1] = make_float2(a0.y, b0.y);
        lin[4*lane+2] = make_float2(a0.z, b0.z);
        lin[4*lane+3] = make_float2(a0.w, b0.w);
        float4 a1 = x0r4[lane],    b1 = x1r4[lane];      // x[0..99] -> lin[300..399]
        lin[300+4*lane  ] = make_float2(a1.x, b1.x);
        lin[300+4*lane+1] = make_float2(a1.y, b1.y);
        lin[300+4*lane+2] = make_float2(a1.z, b1.z);
        lin[300+4*lane+3] = make_float2(a1.w, b1.w);
    }
    fft400<false,true,false>(lin,tmp,lane);
    float2* row0 = g_S + ((size_t)b*200+c0)*400;
    float2* row1 = g_S + ((size_t)b*200+c1)*400;
    for (int k=lane; k<400; k+=32){
        float2 Zk = lin[k];
        float2 Zr = lin[(400-k) & 399];   // (400-k)%400; k=0 -> 0
        row0[k] = make_float2(0.5f*(Zk.x+Zr.x),  0.5f*(Zk.y-Zr.y));
        row1[k] = make_float2(0.5f*(Zk.y+Zr.y), -0.5f*(Zk.x-Zr.x));
    }
}

// ----------------------------- B (warp-private): fused col FFT*H*IFFT ---------------
__global__ void __launch_bounds__(128) kB(int hm){
    __shared__ __align__(16) float2 colb[8][401];
    __shared__ float2 tmpb[4][421];
    int b  = blockIdx.x / 50;
    int k0 = (blockIdx.x % 50) * 8;
    int tid = threadIdx.x;
    const float4* Sb4 = (const float4*)(g_S + (size_t)b*200*400);
    const float2* HT = g_HT + (size_t)hm*160000;

    // stage in (float4 = 2 complex): col[kl][r], r in [0,100) U [300,400)
    for (int idx=tid; idx<800; idx+=128){
        int c = idx>>2, q = idx&3;
        float4 v = Sb4[c*200 + (k0>>1) + q];
        int r = (c<100)? c : c+200;
        colb[2*q  ][r] = make_float2(v.x,v.y);
        colb[2*q+1][r] = make_float2(v.z,v.w);
    }
    __syncthreads();

    int w = tid>>5, lane = tid&31;
    fftB_fused(colb[2*w  ], tmpb[w], lane, HT + (size_t)(k0+2*w  )*400);
    fftB_fused(colb[2*w+1], tmpb[w], lane, HT + (size_t)(k0+2*w+1)*400);
    __syncthreads();

    // stage out (float4), crop rows (no scale: folded into HT)
    float4* S2b4 = (float4*)(g_S2 + (size_t)b*200*400);
    for (int idx=tid; idx<800; idx+=128){
        int c = idx>>2, q = idx&3;
        int r = (c<100)? c : c+200;
        float2 v0 = colb[2*q  ][r];
        float2 v1 = colb[2*q+1][r];
        S2b4[c*200 + (k0>>1) + q] = make_float4(v0.x, v0.y, v1.x, v1.y);
    }
}

// ----------------------------- C: fused row IFFT -> phasor -> row FFT ---------------
__global__ void kC(int l){   // l < 0: no phasor (first boundary)
    __shared__ __align__(16) float2 s_lin[WPB][400];
    __shared__ float2 s_tmp[WPB][421];
    int w = threadIdx.x>>5, lane = threadIdx.x&31;
    int idx = blockIdx.x*WPB + w;
    int b = idx/200, c = idx%200;
    float2* lin = s_lin[w]; float2* tmp = s_tmp[w];
    const float4* S4 = (const float4*)(g_S2 + ((size_t)b*200+c)*400);
    float4* lin4 = (float4*)lin;
    for (int m4=lane;m4<200;m4+=32) lin4[m4]=S4[m4];
    int i = (c<100)? c+100 : c-100;                 // logical row
    const float2* phrow = (l>=0)? (g_PH + (size_t)l*40000 + i*200) : nullptr;
    fftC_fused(lin,tmp,lane,phrow);
    float4* out4 = (float4*)(g_S + ((size_t)b*200+c)*400);
    const float4* l4 = (const float4*)lin;
    for (int m4=lane;m4<200;m4+=32) out4[m4]=l4[m4];
}

// ----------------------------- CF: row IFFT -> intensity -> horizontal 8-sums ------
__global__ void kCF(){
    __shared__ __align__(16) float2 s_lin[WPB][400];
    __shared__ float2 s_tmp[WPB][421];
    int w = threadIdx.x>>5, lane = threadIdx.x&31;
    int idx = blockIdx.x*WPB + w;
    int b = idx/200, c = idx%200;
    float2* lin = s_lin[w]; float2* tmp = s_tmp[w];
    const float4* S4 = (const float4*)(g_S2 + ((size_t)b*200+c)*400);
    float4* lin4 = (float4*)lin;
    for (int m4=lane;m4<200;m4+=32) lin4[m4]=S4[m4];
    fft400<true,false,true>(lin,tmp,lane);          // cropped inverse
    int i = (c<100)? c+100 : c-100;
    float* pbuf = (float*)tmp;                      // tmp is free now; 200 floats
    const float sc = 1.f/400.f;
    for (int cc=lane;cc<200;cc+=32){
        int rc = (cc<100)? cc : cc+200;
        int j  = (cc<100)? cc+100 : cc-100;
        float vx = lin[rc].x*sc, vy = lin[rc].y*sc;
        pbuf[j] = vx*vx + vy*vy;
    }
    __syncwarp();
    if (lane < 25){
        float s = 0.f;
        #pragma unroll
        for (int v=0; v<8; v++) s += pbuf[lane*8+v];
        g_Pp[((size_t)b*200+i)*25 + lane] = s;
    }
}

// ----------------------------- pooling: vertical sum of 8 partials -> [p][b] -------
__global__ void kPool(){
    int idx = blockIdx.x*256 + threadIdx.x;
    if (idx >= 20000) return;
    int b = idx / 625, p = idx % 625;
    int mi = p/25, mj = p%25;
    const float* base = g_Pp + ((size_t)b*200 + mi*8)*25 + mj;
    float s = 0.f;
    #pragma unroll
    for (int u=0;u<8;u++) s += base[u*25];
    g_pool[p*32+b] = s*(1.f/64.f);
}

// ----------------------------- per-window MLP + voting -----------------------------
#define HSTR 513    // padded hid stride (bank-conflict-free)
__global__ void __launch_bounds__(256) kWin(
                     const float* __restrict__ b1, const float* __restrict__ W2,
                     const float* __restrict__ b2, const float* __restrict__ gamma,
                     const float* __restrict__ beta, float* __restrict__ out)
{
    extern __shared__ float dsm[];
    float* swin = dsm;                    // [cell][b] up to 25*32
    float* hid  = dsm + 800;              // [b][hh] 32*HSTR
    float* lg   = dsm + 800 + 32*HSTR;    // [b][o]  32*10
    __shared__ double red1[256], red2[256];
    __shared__ int   pidx[25];
    __shared__ float s_inv, s_c0;
    __shared__ int   s_a[32];
    __shared__ float s_delta[32];

    int wI = blockIdx.x;
    int i = wI/25, j = wI%25;
    int wr = min(5, 25-i), wc = min(5, 25-j);
    int cells = wr*wc;
    int tid = threadIdx.x;
    if (tid < cells) pidx[tid] = (i + tid/wc)*25 + (j + tid%wc);
    __syncthreads();

    double s1 = 0.0, s2 = 0.0;
    for (int q=tid; q<cells*32; q+=256){
        int cell = q>>5, b = q&31;
        float v = g_pool[pidx[cell]*32 + b];
        swin[q] = v;
        s1 += v; s2 += (double)v*(double)v;
    }
    red1[tid]=s1; red2[tid]=s2;
    __syncthreads();
    for (int st=128; st>0; st>>=1){
        if (tid<st){ red1[tid]+=red1[tid+st]; red2[tid]+=red2[tid+st]; }
        __syncthreads();
    }
    if (tid == 0){
        double mu  = red1[0]/20000.0;
        double var = red2[0]/20000.0 - mu*mu;
        float inv = gamma[0]/(float)sqrt(var + 1e-5);
        s_inv = inv;
        s_c0  = beta[0] - (float)mu*inv;
    }
    __syncthreads();
    float inv = s_inv, c0 = s_c0;

    // hid[b][hh] = relu(c0*R1 + inv*<win,W1win> + b1); 8 batches per thread.
    for (int it=0; it<8; it++){
        int task = it*256 + tid;          // 2048 tasks = 4 bgroups x 512 hh
        int hh = task & 511, bg = task >> 9;
        float acc[8];
        #pragma unroll
        for (int u=0;u<8;u++) acc[u]=0.f;
        for (int cell=0; cell<cells; cell++){
            float wv = g_W1T[pidx[cell]*512+hh];
            const float* sw = swin + cell*32 + bg*8;
            #pragma unroll
            for (int u=0;u<8;u++) acc[u] = fmaf(sw[u], wv, acc[u]);
        }
        float base = fmaf(c0, g_R1[hh], b1[hh]);
        #pragma unroll
        for (int u=0;u<8;u++){
            float pre = fmaf(inv, acc[u], base);
            hid[(bg*8+u)*HSTR + hh] = fmaxf(pre, 0.f);
        }
    }
    __syncthreads();

    for (int t=tid; t<320; t+=256){
        int b = t/10, oo = t%10;
        float acc = b2[oo];
        const float* hb = hid + b*HSTR;
        const float* wv = W2 + oo*512;
        for (int hh=0; hh<512; hh++) acc = fmaf(hb[hh], wv[hh], acc);
        lg[b*10+oo] = acc;
    }
    __syncthreads();

    if (tid < 32){
        int b = tid;
        float lmax = lg[b*10], lmin = lg[b*10];
        int am = 0;
        for (int oo=1;oo<10;oo++){
            float v = lg[b*10+oo];
            if (v > lmax){ lmax = v; am = oo; }
            if (v < lmin)  lmin = v;
        }
        float se = 0.f;
        for (int oo=0;oo<10;oo++) se += expf(lg[b*10+oo]-lmax);
        s_a[b] = am;
        s_delta[b] = (1.f - expf(lmin-lmax))/se;  // pmax - pmin
    }
    __syncthreads();
    if (tid == 0){
        int votes[11];
        for (int k=0;k<11;k++) votes[k]=0;
        for (int b=0;b<32;b++) votes[s_a[b]]++;
        int f0 = 0, best = votes[0];
        for (int k=1;k<11;k++) if (votes[k] > best){ best = votes[k]; f0 = k; }
        float sum = 0.f; int cnt = 0;
        for (int b=0;b<32;b++)
            if (s_a[b]==f0 && s_delta[b]!=0.f){ sum += s_delta[b]; cnt++; }
        int fin;
        if (cnt > 0){ float d1 = sum/(float)cnt; fin = (d1 < 0.2f) ? 0 : f0+1; }
        else fin = f0+1;   // delta1 = NaN; NaN < THR is false
        out[wI]       = (fin==0) ? 0.f : (float)fin;
        out[625+wI]   = (fin!=0) ? 1.f : 0.f;
        atomicAdd(&out[1250+fin], 1.0f);   // exact integer counts -> deterministic
    }
}

// ----------------------------- launch -----------------------------
extern "C" void kernel_launch(void* const* d_in, const int* in_sizes, int n_in,
                              void* d_out, int out_size)
{
    int o = (n_in >= 12 && in_sizes[1] == 1) ? 1 : 0;  // skip batch_size scalar if present
    const float*  x     = (const float*) d_in[0];
    const float2* h     = (const float2*)d_in[1+o];
    const float2* h_pro = (const float2*)d_in[2+o];
    const float2* h_det = (const float2*)d_in[3+o];
    const float*  phase = (const float*) d_in[4+o];
    const float*  W1    = (const float*) d_in[5+o];
    const float*  b1    = (const float*) d_in[6+o];
    const float*  W2    = (const float*) d_in[7+o];
    const float*  b2    = (const float*) d_in[8+o];
    const float*  gamma = (const float*) d_in[9+o];
    const float*  beta  = (const float*) d_in[10+o];
    float* out = (float*)d_out;

    cudaFuncSetAttribute(kWin, cudaFuncAttributeMaxDynamicSharedMemorySize,
                         (800 + 32*HSTR + 320)*4);

    kInit<<<1,512>>>(out);
    kPrep<<<625,256>>>(phase);
    kHT <<<dim3(13,13,3),dim3(32,8)>>>(h_pro, h, h_det);   // [0]=h_pro, [1]=h, [2]=h_det
    kT  <<<dim3(20,16),dim3(32,8)>>>(W1);
    kR1 <<<512,128>>>(W1);

    kA0 <<<800,128>>>(x);                  // 2 rows per FFT (real packing)
    kB  <<<1600,128>>>(0);                 // h_pro
    kC  <<<1600,128>>>(-1);
    for (int l=0; l<4; l++){
        kB <<<1600,128>>>(1);              // h (transposed once, reused 4x)
        kC <<<1600,128>>>(l);
    }
    kB  <<<1600,128>>>(2);                 // h_det
    kCF <<<1600,128>>>();

    kPool<<<79,256>>>();

    kWin<<<625,256,(800 + 32*HSTR + 320)*4>>>(b1, W2, b2, gamma, beta, out);
}